// round 12
// baseline (speedup 1.0000x reference)
#include <cuda_runtime.h>
#include <cuda_bf16.h>
#include <cuda_fp16.h>
#include <math.h>
#include <stdint.h>

#define B_   2
#define S_   2048
#define HID_ 2048
#define NH_  32
#define NKV_ 8
#define D_   64

// ---------------------------------------------------------------------------
// Device scratch (no allocations allowed)
// ---------------------------------------------------------------------------
__device__ float g_q [B_*NH_ *S_*D_];   // fp32 pre-RoPE
__device__ float g_k [B_*NKV_*S_*D_];
__device__ float g_v [B_*NKV_*S_*D_];

__device__ __half g_qhi[B_*NH_ *S_*D_], g_qlo[B_*NH_ *S_*D_];  // Q fp16 hi/lo
__device__ __half g_kh [B_*NKV_*S_*D_];                        // K fp16 (hi only)
__device__ __half g_vh [B_*NKV_*S_*D_];

__device__ __half g_xhi [4096*2048], g_xlo [4096*2048];   // X hi/lo (fp16)
__device__ __half g_wh  [3072*2048];                      // Wq|Wk|Wv fp16 (hi only)
__device__ __half g_woh [2048*2048];                      // Wo fp16 (hi only)
__device__ __half g_aohi[4096*2048], g_aolo[4096*2048];   // attention out hi/lo

// ---------------------------------------------------------------------------
// Baseline-PTX tensor helpers (NO tcgen05 — harness builds plain compute_103)
// ---------------------------------------------------------------------------
__device__ __forceinline__ uint32_t s2u(const void* p) {
    uint32_t a;
    asm("{ .reg .u64 t; cvta.to.shared.u64 t, %1; cvt.u32.u64 %0, t; }"
        : "=r"(a) : "l"(p));
    return a;
}
__device__ __forceinline__ void ldsm4(uint32_t* r, uint32_t addr) {
    asm volatile("ldmatrix.sync.aligned.m8n8.x4.shared.b16 {%0,%1,%2,%3}, [%4];"
        : "=r"(r[0]), "=r"(r[1]), "=r"(r[2]), "=r"(r[3]) : "r"(addr));
}
__device__ __forceinline__ void ldsm4t(uint32_t* r, uint32_t addr) {
    asm volatile("ldmatrix.sync.aligned.m8n8.x4.trans.shared.b16 {%0,%1,%2,%3}, [%4];"
        : "=r"(r[0]), "=r"(r[1]), "=r"(r[2]), "=r"(r[3]) : "r"(addr));
}
__device__ __forceinline__ void mma16816h(float* c, const uint32_t* a, const uint32_t* b) {
    asm volatile("mma.sync.aligned.m16n8k16.row.col.f32.f16.f16.f32 "
        "{%0,%1,%2,%3}, {%4,%5,%6,%7}, {%8,%9}, {%0,%1,%2,%3};"
        : "+f"(c[0]), "+f"(c[1]), "+f"(c[2]), "+f"(c[3])
        : "r"(a[0]), "r"(a[1]), "r"(a[2]), "r"(a[3]), "r"(b[0]), "r"(b[1]));
}
__device__ __forceinline__ void mma16816hacc(uint32_t* c, const uint32_t* a, const uint32_t* b) {
    asm volatile("mma.sync.aligned.m16n8k16.row.col.f16.f16.f16.f16 "
        "{%0,%1}, {%2,%3,%4,%5}, {%6,%7}, {%0,%1};"
        : "+r"(c[0]), "+r"(c[1])
        : "r"(a[0]), "r"(a[1]), "r"(a[2]), "r"(a[3]), "r"(b[0]), "r"(b[1]));
}
__device__ __forceinline__ void cp16(uint32_t saddr, const void* gaddr) {
    asm volatile("cp.async.cg.shared.global [%0], [%1], 16;"
                 :: "r"(saddr), "l"(gaddr));
}
__device__ __forceinline__ uint32_t packf16(float lo, float hi) {
    uint32_t d;
    asm("cvt.rn.f16x2.f32 %0, %1, %2;" : "=r"(d) : "f"(hi), "f"(lo));
    return d;
}

// ---------------------------------------------------------------------------
// fp32 -> fp16 hi/lo split, and plain fp16 convert
// ---------------------------------------------------------------------------
__global__ void split_f16(const float* __restrict__ src,
                          __half* __restrict__ hi,
                          __half* __restrict__ lo, int n2)
{
    int i = blockIdx.x * blockDim.x + threadIdx.x;
    if (i >= n2) return;
    float2 v = ((const float2*)src)[i];
    __half h0 = __float2half(v.x);
    __half h1 = __float2half(v.y);
    __half l0 = __float2half(v.x - __half2float(h0));
    __half l1 = __float2half(v.y - __half2float(h1));
    __half2 hh; hh.x = h0; hh.y = h1;
    __half2 ll; ll.x = l0; ll.y = l1;
    ((__half2*)hi)[i] = hh;
    ((__half2*)lo)[i] = ll;
}

__global__ void conv_f16(const float* __restrict__ src,
                         __half* __restrict__ dst, int n2)
{
    int i = blockIdx.x * blockDim.x + threadIdx.x;
    if (i >= n2) return;
    float2 v = ((const float2*)src)[i];
    __half2 h;
    h.x = __float2half(v.x);
    h.y = __float2half(v.y);
    ((__half2*)dst)[i] = h;
}

// ---------------------------------------------------------------------------
// fp32-emulated GEMM on fp16 mma.sync, 2 MMAs/k-step:
//   C = (A_hi + A_lo) * fp16(B)
// CTA tile 256x128, K-chunk 32, 8 warps (4 M x 2 N), warp tile 64x64.
// SMEM/stage: Ahi 16KB | Alo 16KB | B 8KB = 40KB, double buffered (80KB), occ 1.
// Raises MMA-per-smem-byte ~1.5x vs 128x128 (A redundancy 2x, B 2x).
// ---------------------------------------------------------------------------
#define NCHUNK 64      // 2048 / 32
#define GBUF   40960u

__device__ __forceinline__ void load_chunk(
    const __half* __restrict__ Ahi, const __half* __restrict__ Alo,
    const __half* __restrict__ Bh,
    int m0, int n0, uint32_t sb, int buf, int chunk, int tid)
{
    const uint32_t sbase = sb + (uint32_t)buf * GBUF;
    #pragma unroll
    for (int j = 0; j < 4; ++j) {                 // A: 256 rows x 4 c-groups
        int u = tid + j * 256;
        int r = u >> 2, c = u & 3;
        uint32_t so = sbase + (uint32_t)r * 64u
                    + ((uint32_t)(c ^ ((r >> 1) & 3)) << 4);
        const size_t goff = (size_t)(m0 + r) * 2048u + chunk * 32 + c * 8;
        cp16(so,           &Ahi[goff]);
        cp16(so + 16384u,  &Alo[goff]);
    }
    #pragma unroll
    for (int j = 0; j < 2; ++j) {                 // B: 128 rows x 4 c-groups
        int u = tid + j * 256;
        int r = u >> 2, c = u & 3;
        uint32_t so = sbase + 32768u + (uint32_t)r * 64u
                    + ((uint32_t)(c ^ ((r >> 1) & 3)) << 4);
        cp16(so, &Bh[(size_t)(n0 + r) * 2048u + chunk * 32 + c * 8]);
    }
    asm volatile("cp.async.commit_group;" ::: "memory");
}

__global__ __launch_bounds__(256, 1) void gemm_mma(
    const __half* __restrict__ Ahi, const __half* __restrict__ Alo,
    const __half* __restrict__ Bh,
    int mode, float* __restrict__ outp)
{
    extern __shared__ char smem[];
    const uint32_t sb = s2u(smem);
    const int tid  = threadIdx.x;
    const int lane = tid & 31;
    const int wid  = tid >> 5;
    const int wm   = wid & 3;      // 4 warps along M, 64 rows each
    const int wn   = wid >> 2;     // 2 warps along N, 64 cols each
    const int m0   = blockIdx.y << 8;   // 256-row tiles
    const int n0   = blockIdx.x << 7;   // 128-col tiles

    float acc[4][8][4];
    #pragma unroll
    for (int mt = 0; mt < 4; ++mt)
        #pragma unroll
        for (int nt = 0; nt < 8; ++nt)
            #pragma unroll
            for (int j = 0; j < 4; ++j) acc[mt][nt][j] = 0.f;

    load_chunk(Ahi, Alo, Bh, m0, n0, sb, 0, 0, tid);

    for (int c = 0; c < NCHUNK; ++c) {
        const int buf = c & 1;
        if (c + 1 < NCHUNK) {
            load_chunk(Ahi, Alo, Bh, m0, n0, sb, buf ^ 1, c + 1, tid);
            asm volatile("cp.async.wait_group 1;" ::: "memory");
        } else {
            asm volatile("cp.async.wait_group 0;" ::: "memory");
        }
        __syncthreads();

        const uint32_t base = sb + (uint32_t)buf * GBUF;
        #pragma unroll
        for (int ks = 0; ks < 2; ++ks) {
            const int cg = ks * 2 + (lane >> 4);
            uint32_t ah[4][4], al[4][4];
            #pragma unroll
            for (int mt = 0; mt < 4; ++mt) {
                int r = wm * 64 + mt * 16 + (lane & 15);
                uint32_t sw = (uint32_t)(cg ^ ((r >> 1) & 3)) << 4;
                ldsm4(ah[mt], base +      0u + (uint32_t)r * 64u + sw);
                ldsm4(al[mt], base + 16384u + (uint32_t)r * 64u + sw);
            }
            uint32_t bh[8][2];
            #pragma unroll
            for (int nt2 = 0; nt2 < 4; ++nt2) {
                int r = wn * 64 + nt2 * 16 + (lane & 15);
                uint32_t sw = (uint32_t)(cg ^ ((r >> 1) & 3)) << 4;
                uint32_t t[4];
                ldsm4(t, base + 32768u + (uint32_t)r * 64u + sw);
                bh[nt2*2  ][0] = t[0]; bh[nt2*2  ][1] = t[2];
                bh[nt2*2+1][0] = t[1]; bh[nt2*2+1][1] = t[3];
            }
            #pragma unroll
            for (int mt = 0; mt < 4; ++mt)
                #pragma unroll
                for (int nt = 0; nt < 8; ++nt) {
                    mma16816h(acc[mt][nt], ah[mt], bh[nt]);
                    mma16816h(acc[mt][nt], al[mt], bh[nt]);
                }
        }
        __syncthreads();
    }

    #pragma unroll
    for (int mt = 0; mt < 4; ++mt) {
        #pragma unroll
        for (int half = 0; half < 2; ++half) {
            const int m  = m0 + wm * 64 + mt * 16 + (lane >> 2) + half * 8;
            const int bb = m >> 11;
            const int s  = m & 2047;
            #pragma unroll
            for (int nt = 0; nt < 8; ++nt) {
                const int n = n0 + wn * 64 + nt * 8 + (lane & 3) * 2;
                float2 v = make_float2(acc[mt][nt][half*2], acc[mt][nt][half*2+1]);
                if (mode == 0) {
                    if (n < 2048) {
                        int h = n >> 6, d = n & 63;
                        *(float2*)&g_q[(((size_t)bb*NH_ + h)*S_ + s)*D_ + d] = v;
                    } else if (n < 2560) {
                        int nn = n - 2048; int h = nn >> 6, d = nn & 63;
                        *(float2*)&g_k[(((size_t)bb*NKV_ + h)*S_ + s)*D_ + d] = v;
                    } else {
                        int nn = n - 2560; int h = nn >> 6, d = nn & 63;
                        *(float2*)&g_v[(((size_t)bb*NKV_ + h)*S_ + s)*D_ + d] = v;
                    }
                } else {
                    *(float2*)&outp[(size_t)m * 2048 + n] = v;
                }
            }
        }
    }
}

// ---------------------------------------------------------------------------
// RoPE + fp16 hi/lo split.  writelo=1 -> writes hi+lo (Q); 0 -> hi only (K).
// ---------------------------------------------------------------------------
__global__ void rope_split_h(const float* __restrict__ cosp,
                             const float* __restrict__ sinp,
                             const float* __restrict__ src,
                             __half* __restrict__ dhi,
                             __half* __restrict__ dlo,
                             int nheads, int total, int writelo)
{
    int idx = blockIdx.x * blockDim.x + threadIdx.x;
    if (idx >= total) return;
    int dp = idx & 31;
    int t  = idx >> 5;
    int s  = t & (S_ - 1);
    t >>= 11;
    int h = t % nheads;
    int b = t / nheads;

    int base  = ((b*nheads + h)*S_ + s)*D_;
    int cbase = (b*S_ + s)*D_;

    float x1 = src[base + dp];
    float x2 = src[base + dp + 32];
    float c1 = cosp[cbase + dp],  c2 = cosp[cbase + dp + 32];
    float s1 = sinp[cbase + dp],  s2 = sinp[cbase + dp + 32];
    float y1 = x1*c1 - x2*s1;
    float y2 = x2*c2 + x1*s2;

    __half h1 = __float2half(y1);
    __half h2 = __float2half(y2);
    dhi[base + dp]      = h1;
    dhi[base + dp + 32] = h2;
    if (writelo) {
        dlo[base + dp]      = __float2half(y1 - __half2float(h1));
        dlo[base + dp + 32] = __float2half(y2 - __half2float(h2));
    }
}

// ---------------------------------------------------------------------------
// Flash attention on mma.sync (unchanged from passing R11 kernel).
// S = (Qhi + Qlo) * fp16(K): qh*kh f32 acc + ql*kh f16 acc; softmax fp32;
// P*V fp16 with f32 acc.
// ---------------------------------------------------------------------------
#define FA_BUF  16384u
#define FA_SMEM (32768 + 2*16384)

__device__ __forceinline__ void fa_load_kv(const __half* kh, const __half* vb,
                                           int k0, uint32_t sb, int buf, int tid)
{
    #pragma unroll
    for (int j = 0; j < 2; ++j) {
        int u = tid + j * 256;          // 0..511
        int r = u >> 3, c = u & 7;
        uint32_t so = sb + 32768u + (uint32_t)buf * FA_BUF
                    + (uint32_t)r * 128u + ((uint32_t)(c ^ (r & 7)) << 4);
        cp16(so,         &kh[(size_t)(k0 + r) * 64u + c * 8]);
        cp16(so + 8192u, &vb[(size_t)(k0 + r) * 64u + c * 8]);
    }
    asm volatile("cp.async.commit_group;" ::: "memory");
}

__global__ __launch_bounds__(256, 1) void flash_mma()
{
    extern __shared__ char smem[];
    const uint32_t sb = s2u(smem);
    const int tid  = threadIdx.x;
    const int lane = tid & 31;
    const int wid  = tid >> 5;
    const int q0   = blockIdx.x << 7;
    const int h    = blockIdx.y;
    const int b    = blockIdx.z;
    const int kvh  = h >> 2;

    const __half* qhib = g_qhi + ((size_t)(b*NH_ + h)*S_ + q0)*D_;
    const __half* qlob = g_qlo + ((size_t)(b*NH_ + h)*S_ + q0)*D_;
    const __half* khb  = g_kh  + ((size_t)(b*NKV_ + kvh)*S_)*D_;
    const __half* vbb  = g_vh  + ((size_t)(b*NKV_ + kvh)*S_)*D_;

    #pragma unroll
    for (int j = 0; j < 4; ++j) {
        int u = tid + j * 256;              // 0..1023
        int r = u >> 3, c = u & 7;
        uint32_t so = (uint32_t)r * 128u + ((uint32_t)(c ^ (r & 7)) << 4);
        cp16(sb + so,          &qhib[(size_t)r * 64u + c * 8]);
        cp16(sb + 16384u + so, &qlob[(size_t)r * 64u + c * 8]);
    }
    fa_load_kv(khb, vbb, 0, sb, 0, tid);   // group: [Q + KV0]

    float oacc[8][4];
    #pragma unroll
    for (int dt = 0; dt < 8; ++dt)
        #pragma unroll
        for (int j = 0; j < 4; ++j) oacc[dt][j] = 0.f;
    float m0 = -INFINITY, m1 = -INFINITY, l0 = 0.f, l1 = 0.f;

    const int wrow = wid * 16;
    const uint32_t KH = sb + 32768u;

    for (int c = 0; c < 32; ++c) {
        const int buf = c & 1;
        if (c + 1 < 32) {
            fa_load_kv(khb, vbb, (c + 1) * 64, sb, buf ^ 1, tid);
            asm volatile("cp.async.wait_group 1;" ::: "memory");
        } else {
            asm volatile("cp.async.wait_group 0;" ::: "memory");
        }
        __syncthreads();

        const uint32_t kh = KH + (uint32_t)buf * FA_BUF;
        const uint32_t vv = kh + 8192u;

        float sacc[8][4];
        uint32_t shl[8][2];
        #pragma unroll
        for (int nt = 0; nt < 8; ++nt) {
            #pragma unroll
            for (int j = 0; j < 4; ++j) sacc[nt][j] = 0.f;
            shl[nt][0] = 0u; shl[nt][1] = 0u;
        }

        #pragma unroll
        for (int ks = 0; ks < 4; ++ks) {
            const int cg = ks * 2 + (lane >> 4);
            int rq = wrow + (lane & 15);
            uint32_t swq = (uint32_t)(cg ^ (rq & 7)) << 4;
            uint32_t aqh[4], aql[4];
            ldsm4(aqh, sb +          (uint32_t)rq * 128u + swq);
            ldsm4(aql, sb + 16384u + (uint32_t)rq * 128u + swq);
            uint32_t bh[8][2];
            #pragma unroll
            for (int kb = 0; kb < 4; ++kb) {
                int rk = kb * 16 + (lane & 15);
                uint32_t swk = (uint32_t)(cg ^ (rk & 7)) << 4;
                uint32_t t[4];
                ldsm4(t, kh + (uint32_t)rk * 128u + swk);
                bh[kb*2  ][0] = t[0]; bh[kb*2  ][1] = t[2];
                bh[kb*2+1][0] = t[1]; bh[kb*2+1][1] = t[3];
            }
            #pragma unroll
            for (int nt = 0; nt < 8; ++nt) mma16816h(sacc[nt], aqh, bh[nt]);
            #pragma unroll
            for (int nt = 0; nt < 8; ++nt) mma16816hacc(shl[nt], aql, bh[nt]);
        }
        #pragma unroll
        for (int nt = 0; nt < 8; ++nt) {
            __half2 p01 = *(__half2*)&shl[nt][0];
            __half2 p23 = *(__half2*)&shl[nt][1];
            sacc[nt][0] += __half2float(p01.x);
            sacc[nt][1] += __half2float(p01.y);
            sacc[nt][2] += __half2float(p23.x);
            sacc[nt][3] += __half2float(p23.y);
        }

        float mx0 = -INFINITY, mx1 = -INFINITY;
        #pragma unroll
        for (int nt = 0; nt < 8; ++nt) {
            #pragma unroll
            for (int j = 0; j < 4; ++j) sacc[nt][j] *= 0.125f;
            mx0 = fmaxf(mx0, fmaxf(sacc[nt][0], sacc[nt][1]));
            mx1 = fmaxf(mx1, fmaxf(sacc[nt][2], sacc[nt][3]));
        }
        #pragma unroll
        for (int off = 1; off < 4; off <<= 1) {
            mx0 = fmaxf(mx0, __shfl_xor_sync(0xffffffffu, mx0, off));
            mx1 = fmaxf(mx1, __shfl_xor_sync(0xffffffffu, mx1, off));
        }
        float mn0 = fmaxf(m0, mx0), mn1 = fmaxf(m1, mx1);
        float sc0 = __expf(m0 - mn0), sc1 = __expf(m1 - mn1);
        m0 = mn0; m1 = mn1;
        float rs0 = 0.f, rs1 = 0.f;
        #pragma unroll
        for (int nt = 0; nt < 8; ++nt) {
            sacc[nt][0] = __expf(sacc[nt][0] - mn0);
            sacc[nt][1] = __expf(sacc[nt][1] - mn0);
            sacc[nt][2] = __expf(sacc[nt][2] - mn1);
            sacc[nt][3] = __expf(sacc[nt][3] - mn1);
            rs0 += sacc[nt][0] + sacc[nt][1];
            rs1 += sacc[nt][2] + sacc[nt][3];
        }
        #pragma unroll
        for (int off = 1; off < 4; off <<= 1) {
            rs0 += __shfl_xor_sync(0xffffffffu, rs0, off);
            rs1 += __shfl_xor_sync(0xffffffffu, rs1, off);
        }
        l0 = l0 * sc0 + rs0;
        l1 = l1 * sc1 + rs1;
        #pragma unroll
        for (int dt = 0; dt < 8; ++dt) {
            oacc[dt][0] *= sc0; oacc[dt][1] *= sc0;
            oacc[dt][2] *= sc1; oacc[dt][3] *= sc1;
        }

        #pragma unroll
        for (int ks = 0; ks < 4; ++ks) {
            uint32_t pa[4];
            pa[0] = packf16(sacc[2*ks  ][0], sacc[2*ks  ][1]);
            pa[1] = packf16(sacc[2*ks  ][2], sacc[2*ks  ][3]);
            pa[2] = packf16(sacc[2*ks+1][0], sacc[2*ks+1][1]);
            pa[3] = packf16(sacc[2*ks+1][2], sacc[2*ks+1][3]);
            int rv = ks * 16 + (lane & 7) + ((lane >> 3) & 1) * 8;
            uint32_t rvb = vv + (uint32_t)rv * 128u;
            uint32_t bv[8][2];
            #pragma unroll
            for (int dp = 0; dp < 4; ++dp) {
                int cv = dp * 2 + (lane >> 4);
                uint32_t tv[4];
                ldsm4t(tv, rvb + ((uint32_t)(cv ^ (rv & 7)) << 4));
                bv[dp*2  ][0] = tv[0]; bv[dp*2  ][1] = tv[1];
                bv[dp*2+1][0] = tv[2]; bv[dp*2+1][1] = tv[3];
            }
            #pragma unroll
            for (int dt = 0; dt < 8; ++dt)
                mma16816h(oacc[dt], pa, bv[dt]);
        }
        __syncthreads();
    }

    float inv0 = 1.f / l0, inv1 = 1.f / l1;
    const int r0g = q0 + wrow + (lane >> 2);
    const size_t m0i = ((size_t)(b * S_ + r0g)) * 2048u + h * 64;
    const size_t m1i = m0i + 8u * 2048u;
    #pragma unroll
    for (int dt = 0; dt < 8; ++dt) {
        int d = dt * 8 + (lane & 3) * 2;
        float v0 = oacc[dt][0] * inv0, v1 = oacc[dt][1] * inv0;
        float v2 = oacc[dt][2] * inv1, v3 = oacc[dt][3] * inv1;
        __half2 h01, h23, lo01, lo23;
        h01.x = __float2half(v0); h01.y = __float2half(v1);
        h23.x = __float2half(v2); h23.y = __float2half(v3);
        lo01.x = __float2half(v0 - __half2float(h01.x));
        lo01.y = __float2half(v1 - __half2float(h01.y));
        lo23.x = __float2half(v2 - __half2float(h23.x));
        lo23.y = __float2half(v3 - __half2float(h23.y));
        *(__half2*)&g_aohi[m0i + d] = h01;
        *(__half2*)&g_aolo[m0i + d] = lo01;
        *(__half2*)&g_aohi[m1i + d] = h23;
        *(__half2*)&g_aolo[m1i + d] = lo23;
    }
}

// ---------------------------------------------------------------------------
extern "C" void kernel_launch(void* const* d_in, const int* in_sizes, int n_in,
                              void* d_out, int out_size)
{
    (void)in_sizes; (void)n_in; (void)out_size;
    const float* hs   = (const float*)d_in[0];
    const float* cosp = (const float*)d_in[1];
    const float* sinp = (const float*)d_in[2];
    const float* Wq = (const float*)d_in[4];
    const float* Wk = (const float*)d_in[5];
    const float* Wv = (const float*)d_in[6];
    const float* Wo = (const float*)d_in[7];
    float* out = (float*)d_out;

    __half *xhi, *xlo, *wh, *woh, *aohi, *aolo, *vh, *qhi, *qlo, *kh;
    float *qf, *kf, *vf;
    cudaGetSymbolAddress((void**)&xhi,  g_xhi);  cudaGetSymbolAddress((void**)&xlo,  g_xlo);
    cudaGetSymbolAddress((void**)&wh,   g_wh);   cudaGetSymbolAddress((void**)&woh,  g_woh);
    cudaGetSymbolAddress((void**)&aohi, g_aohi); cudaGetSymbolAddress((void**)&aolo, g_aolo);
    cudaGetSymbolAddress((void**)&qhi, g_qhi);   cudaGetSymbolAddress((void**)&qlo, g_qlo);
    cudaGetSymbolAddress((void**)&kh,  g_kh);
    cudaGetSymbolAddress((void**)&vh,  g_vh);
    cudaGetSymbolAddress((void**)&qf,  g_q);
    cudaGetSymbolAddress((void**)&kf,  g_k);
    cudaGetSymbolAddress((void**)&vf,  g_v);

    const int T = 256;
    // 1) X -> fp16 hi/lo; W, Wo -> fp16 (hi only)
    split_f16<<<(4096*2048/2 + T-1)/T, T>>>(hs, xhi, xlo, 4096*2048/2);
    conv_f16 <<<(2048*2048/2 + T-1)/T, T>>>(Wq, wh,             2048*2048/2);
    conv_f16 <<<( 512*2048/2 + T-1)/T, T>>>(Wk, wh + 2048*2048,  512*2048/2);
    conv_f16 <<<( 512*2048/2 + T-1)/T, T>>>(Wv, wh + 2560*2048,  512*2048/2);
    conv_f16 <<<(2048*2048/2 + T-1)/T, T>>>(Wo, woh, 2048*2048/2);

    // 2) QKV projection (2-MMA fp16 emulated fp32), 256x128 tiles
    const int gsmem = 2 * (int)GBUF;   // 80KB
    cudaFuncSetAttribute(gemm_mma, cudaFuncAttributeMaxDynamicSharedMemorySize, gsmem);
    dim3 g1(3072/128, 4096/256);
    gemm_mma<<<g1, 256, gsmem>>>(xhi, xlo, wh, 0, nullptr);

    // 3) RoPE + fp16 split: Q -> hi/lo, K -> hi only; V -> fp16
    int nq = B_*NH_ *S_*32;
    int nk = B_*NKV_*S_*32;
    rope_split_h<<<(nq + T-1)/T, T>>>(cosp, sinp, qf, qhi, qlo, NH_,  nq, 1);
    rope_split_h<<<(nk + T-1)/T, T>>>(cosp, sinp, kf, kh,  nullptr, NKV_, nk, 0);
    conv_f16<<<(B_*NKV_*S_*D_/2 + T-1)/T, T>>>(vf, vh, B_*NKV_*S_*D_/2);

    // 4) Flash attention on tensor cores (unchanged)
    cudaFuncSetAttribute(flash_mma, cudaFuncAttributeMaxDynamicSharedMemorySize, FA_SMEM);
    dim3 g2(S_/128, NH_, B_);
    flash_mma<<<g2, 256, FA_SMEM>>>();

    // 5) O-projection (2-MMA fp16 emulated fp32), 256x128 tiles
    dim3 g3(2048/128, 4096/256);
    gemm_mma<<<g3, 256, gsmem>>>(aohi, aolo, woh, 1, out);
}

// round 13
// speedup vs baseline: 1.0586x; 1.0586x over previous
#include <cuda_runtime.h>
#include <cuda_bf16.h>
#include <cuda_fp16.h>
#include <math.h>
#include <stdint.h>

#define B_   2
#define S_   2048
#define HID_ 2048
#define NH_  32
#define NKV_ 8
#define D_   64

// ---------------------------------------------------------------------------
// Device scratch (no allocations allowed)
// ---------------------------------------------------------------------------
__device__ __half g_qhi[B_*NH_ *S_*D_], g_qlo[B_*NH_ *S_*D_];  // Q fp16 hi/lo (post-RoPE)
__device__ __half g_kh [B_*NKV_*S_*D_];                        // K fp16 (post-RoPE)
__device__ __half g_vh [B_*NKV_*S_*D_];

__device__ __half g_xhi [4096*2048], g_xlo [4096*2048];   // X hi/lo (fp16)
__device__ __half g_wh  [3072*2048];                      // Wq|Wk|Wv fp16
__device__ __half g_woh [2048*2048];                      // Wo fp16
__device__ __half g_aohi[4096*2048], g_aolo[4096*2048];   // attention out hi/lo

// ---------------------------------------------------------------------------
// Baseline-PTX tensor helpers (NO tcgen05 — harness builds plain compute_103)
// ---------------------------------------------------------------------------
__device__ __forceinline__ uint32_t s2u(const void* p) {
    uint32_t a;
    asm("{ .reg .u64 t; cvta.to.shared.u64 t, %1; cvt.u32.u64 %0, t; }"
        : "=r"(a) : "l"(p));
    return a;
}
__device__ __forceinline__ void ldsm4(uint32_t* r, uint32_t addr) {
    asm volatile("ldmatrix.sync.aligned.m8n8.x4.shared.b16 {%0,%1,%2,%3}, [%4];"
        : "=r"(r[0]), "=r"(r[1]), "=r"(r[2]), "=r"(r[3]) : "r"(addr));
}
__device__ __forceinline__ void ldsm4t(uint32_t* r, uint32_t addr) {
    asm volatile("ldmatrix.sync.aligned.m8n8.x4.trans.shared.b16 {%0,%1,%2,%3}, [%4];"
        : "=r"(r[0]), "=r"(r[1]), "=r"(r[2]), "=r"(r[3]) : "r"(addr));
}
__device__ __forceinline__ void mma16816h(float* c, const uint32_t* a, const uint32_t* b) {
    asm volatile("mma.sync.aligned.m16n8k16.row.col.f32.f16.f16.f32 "
        "{%0,%1,%2,%3}, {%4,%5,%6,%7}, {%8,%9}, {%0,%1,%2,%3};"
        : "+f"(c[0]), "+f"(c[1]), "+f"(c[2]), "+f"(c[3])
        : "r"(a[0]), "r"(a[1]), "r"(a[2]), "r"(a[3]), "r"(b[0]), "r"(b[1]));
}
__device__ __forceinline__ void mma16816hacc(uint32_t* c, const uint32_t* a, const uint32_t* b) {
    asm volatile("mma.sync.aligned.m16n8k16.row.col.f16.f16.f16.f16 "
        "{%0,%1}, {%2,%3,%4,%5}, {%6,%7}, {%0,%1};"
        : "+r"(c[0]), "+r"(c[1])
        : "r"(a[0]), "r"(a[1]), "r"(a[2]), "r"(a[3]), "r"(b[0]), "r"(b[1]));
}
__device__ __forceinline__ void cp16(uint32_t saddr, const void* gaddr) {
    asm volatile("cp.async.cg.shared.global [%0], [%1], 16;"
                 :: "r"(saddr), "l"(gaddr));
}
__device__ __forceinline__ uint32_t packf16(float lo, float hi) {
    uint32_t d;
    asm("cvt.rn.f16x2.f32 %0, %1, %2;" : "=r"(d) : "f"(hi), "f"(lo));
    return d;
}
__device__ __forceinline__ __half2 mkh2(float a, float b) {
    __half2 h; h.x = __float2half(a); h.y = __float2half(b); return h;
}

// ---------------------------------------------------------------------------
// Prep kernels: X -> fp16 hi/lo split; all weights -> fp16 in ONE kernel.
// ---------------------------------------------------------------------------
__global__ void split_f16(const float* __restrict__ src,
                          __half* __restrict__ hi,
                          __half* __restrict__ lo, int n2)
{
    int i = blockIdx.x * blockDim.x + threadIdx.x;
    if (i >= n2) return;
    float2 v = ((const float2*)src)[i];
    __half h0 = __float2half(v.x);
    __half h1 = __float2half(v.y);
    __half2 hh; hh.x = h0; hh.y = h1;
    __half2 ll; ll.x = __float2half(v.x - __half2float(h0));
    ll.y = __float2half(v.y - __half2float(h1));
    ((__half2*)hi)[i] = hh;
    ((__half2*)lo)[i] = ll;
}

#define WQ_F2 (2048*2048/2)
#define WK_F2 ( 512*2048/2)
__global__ void conv_w(const float* __restrict__ Wq, const float* __restrict__ Wk,
                       const float* __restrict__ Wv, const float* __restrict__ Wo,
                       __half* __restrict__ wh, __half* __restrict__ woh)
{
    int i = blockIdx.x * blockDim.x + threadIdx.x;   // float2 index
    const float2* src; __half* dst; int j;
    if (i < WQ_F2)                        { src = (const float2*)Wq; dst = wh;                  j = i; }
    else if (i < WQ_F2 + WK_F2)           { src = (const float2*)Wk; dst = wh + 2048*2048;      j = i - WQ_F2; }
    else if (i < WQ_F2 + 2*WK_F2)         { src = (const float2*)Wv; dst = wh + 2560*2048;      j = i - WQ_F2 - WK_F2; }
    else if (i < 2*WQ_F2 + 2*WK_F2)       { src = (const float2*)Wo; dst = woh;                 j = i - WQ_F2 - 2*WK_F2; }
    else return;
    float2 v = src[j];
    __half2 h; h.x = __float2half(v.x); h.y = __float2half(v.y);
    ((__half2*)dst)[j] = h;
}

// ---------------------------------------------------------------------------
// fp32-emulated GEMM on fp16 mma.sync, 2 MMAs/k-step (R8 shape: 128x128, occ 2):
//   C = (A_hi + A_lo) * fp16(B)
// mode 0: epilogue applies RoPE (fp32) and writes qhi/qlo, kh, vh fp16 directly.
// mode 1: writes fp32 outp.
// ---------------------------------------------------------------------------
#define NCHUNK 64      // 2048 / 32

__device__ __forceinline__ void load_chunk(
    const __half* __restrict__ Ahi, const __half* __restrict__ Alo,
    const __half* __restrict__ Bh,
    int m0, int n0, uint32_t sb, int buf, int chunk, int tid)
{
    const __half* srcs[3] = {Ahi, Alo, Bh};
    const int r0s[3] = {m0, m0, n0};
    #pragma unroll
    for (int op = 0; op < 3; ++op) {
        #pragma unroll
        for (int j = 0; j < 2; ++j) {
            int u = tid + j * 256;
            int r = u >> 2, c = u & 3;
            const __half* g =
                srcs[op] + (size_t)(r0s[op] + r) * 2048u + chunk * 32 + c * 8;
            uint32_t so = sb + (uint32_t)buf * 24576u + (uint32_t)op * 8192u
                        + (uint32_t)r * 64u
                        + ((uint32_t)(c ^ ((r >> 1) & 3)) << 4);
            cp16(so, g);
        }
    }
    asm volatile("cp.async.commit_group;" ::: "memory");
}

__global__ __launch_bounds__(256, 2) void gemm_mma(
    const __half* __restrict__ Ahi, const __half* __restrict__ Alo,
    const __half* __restrict__ Bh,
    const float* __restrict__ cosp, const float* __restrict__ sinp,
    int mode, float* __restrict__ outp)
{
    extern __shared__ char smem[];
    const uint32_t sb = s2u(smem);
    const int tid  = threadIdx.x;
    const int lane = tid & 31;
    const int wid  = tid >> 5;
    const int wm   = wid & 3;
    const int wn   = wid >> 2;
    const int m0   = blockIdx.y << 7;
    const int n0   = blockIdx.x << 7;

    float acc[2][8][4];
    #pragma unroll
    for (int mt = 0; mt < 2; ++mt)
        #pragma unroll
        for (int nt = 0; nt < 8; ++nt)
            #pragma unroll
            for (int j = 0; j < 4; ++j) acc[mt][nt][j] = 0.f;

    load_chunk(Ahi, Alo, Bh, m0, n0, sb, 0, 0, tid);

    for (int c = 0; c < NCHUNK; ++c) {
        const int buf = c & 1;
        if (c + 1 < NCHUNK) {
            load_chunk(Ahi, Alo, Bh, m0, n0, sb, buf ^ 1, c + 1, tid);
            asm volatile("cp.async.wait_group 1;" ::: "memory");
        } else {
            asm volatile("cp.async.wait_group 0;" ::: "memory");
        }
        __syncthreads();

        const uint32_t base = sb + (uint32_t)buf * 24576u;
        #pragma unroll
        for (int ks = 0; ks < 2; ++ks) {
            const int cg = ks * 2 + (lane >> 4);
            uint32_t ah[2][4], al[2][4];
            #pragma unroll
            for (int mt = 0; mt < 2; ++mt) {
                int r = wm * 32 + mt * 16 + (lane & 15);
                uint32_t sw = (uint32_t)(cg ^ ((r >> 1) & 3)) << 4;
                ldsm4(ah[mt], base +     0u + (uint32_t)r * 64u + sw);
                ldsm4(al[mt], base + 8192u + (uint32_t)r * 64u + sw);
            }
            uint32_t bh[8][2];
            #pragma unroll
            for (int nt2 = 0; nt2 < 4; ++nt2) {
                int r = wn * 64 + nt2 * 16 + (lane & 15);
                uint32_t sw = (uint32_t)(cg ^ ((r >> 1) & 3)) << 4;
                uint32_t t[4];
                ldsm4(t, base + 16384u + (uint32_t)r * 64u + sw);
                bh[nt2*2  ][0] = t[0]; bh[nt2*2  ][1] = t[2];
                bh[nt2*2+1][0] = t[1]; bh[nt2*2+1][1] = t[3];
            }
            #pragma unroll
            for (int mt = 0; mt < 2; ++mt)
                #pragma unroll
                for (int nt = 0; nt < 8; ++nt) {
                    mma16816h(acc[mt][nt], ah[mt], bh[nt]);
                    mma16816h(acc[mt][nt], al[mt], bh[nt]);
                }
        }
        __syncthreads();
    }

    if (mode == 1) {
        #pragma unroll
        for (int mt = 0; mt < 2; ++mt)
            #pragma unroll
            for (int half = 0; half < 2; ++half) {
                const int m = m0 + wm * 32 + mt * 16 + (lane >> 2) + half * 8;
                #pragma unroll
                for (int nt = 0; nt < 8; ++nt) {
                    const int n = n0 + wn * 64 + nt * 8 + (lane & 3) * 2;
                    *(float2*)&outp[(size_t)m * 2048 + n] =
                        make_float2(acc[mt][nt][half*2], acc[mt][nt][half*2+1]);
                }
            }
        return;
    }

    // mode 0: fused RoPE (Q/K) + fp16 conversion.  Thread holds cols d and d+32
    // (nt and nt+4), so the RoPE pair is thread-local.
    #pragma unroll
    for (int mt = 0; mt < 2; ++mt) {
        #pragma unroll
        for (int half = 0; half < 2; ++half) {
            const int m  = m0 + wm * 32 + mt * 16 + (lane >> 2) + half * 8;
            const int bb = m >> 11;
            const int s  = m & 2047;
            const size_t cb = ((size_t)bb * S_ + s) * D_;
            #pragma unroll
            for (int ntp = 0; ntp < 4; ++ntp) {
                const int n = n0 + wn * 64 + ntp * 8 + (lane & 3) * 2;
                float x1a = acc[mt][ntp  ][half*2], x1b = acc[mt][ntp  ][half*2+1];
                float x2a = acc[mt][ntp+4][half*2], x2b = acc[mt][ntp+4][half*2+1];
                if (n < 2560) {
                    // Q or K: RoPE in fp32, then fp16 (hi/lo for Q, hi for K)
                    const int nn = (n < 2048) ? n : n - 2048;
                    const int h = nn >> 6, d = nn & 63;    // d in [0,30]
                    float2 c1 = *(const float2*)&cosp[cb + d];
                    float2 c2 = *(const float2*)&cosp[cb + d + 32];
                    float2 s1 = *(const float2*)&sinp[cb + d];
                    float2 s2 = *(const float2*)&sinp[cb + d + 32];
                    float y1a = x1a*c1.x - x2a*s1.x;
                    float y1b = x1b*c1.y - x2b*s1.y;
                    float y2a = x2a*c2.x + x1a*s2.x;
                    float y2b = x2b*c2.y + x1b*s2.y;
                    if (n < 2048) {
                        const size_t base = (((size_t)bb*NH_ + h)*S_ + s)*D_ + d;
                        __half2 h1 = mkh2(y1a, y1b), h2v = mkh2(y2a, y2b);
                        *(__half2*)&g_qhi[base]      = h1;
                        *(__half2*)&g_qhi[base + 32] = h2v;
                        *(__half2*)&g_qlo[base] =
                            mkh2(y1a - __half2float(h1.x),  y1b - __half2float(h1.y));
                        *(__half2*)&g_qlo[base + 32] =
                            mkh2(y2a - __half2float(h2v.x), y2b - __half2float(h2v.y));
                    } else {
                        const size_t base = (((size_t)bb*NKV_ + h)*S_ + s)*D_ + d;
                        *(__half2*)&g_kh[base]      = mkh2(y1a, y1b);
                        *(__half2*)&g_kh[base + 32] = mkh2(y2a, y2b);
                    }
                } else {
                    // V: plain fp16
                    const int nn = n - 2560;
                    const int h = nn >> 6, d = nn & 63;
                    const size_t base = (((size_t)bb*NKV_ + h)*S_ + s)*D_ + d;
                    *(__half2*)&g_vh[base]      = mkh2(x1a, x1b);
                    *(__half2*)&g_vh[base + 32] = mkh2(x2a, x2b);
                }
            }
        }
    }
}

// ---------------------------------------------------------------------------
// Flash attention on mma.sync (byte-identical to passing R11 kernel).
// ---------------------------------------------------------------------------
#define FA_BUF  16384u
#define FA_SMEM (32768 + 2*16384)

__device__ __forceinline__ void fa_load_kv(const __half* kh, const __half* vb,
                                           int k0, uint32_t sb, int buf, int tid)
{
    #pragma unroll
    for (int j = 0; j < 2; ++j) {
        int u = tid + j * 256;          // 0..511
        int r = u >> 3, c = u & 7;
        uint32_t so = sb + 32768u + (uint32_t)buf * FA_BUF
                    + (uint32_t)r * 128u + ((uint32_t)(c ^ (r & 7)) << 4);
        cp16(so,         &kh[(size_t)(k0 + r) * 64u + c * 8]);
        cp16(so + 8192u, &vb[(size_t)(k0 + r) * 64u + c * 8]);
    }
    asm volatile("cp.async.commit_group;" ::: "memory");
}

__global__ __launch_bounds__(256, 1) void flash_mma()
{
    extern __shared__ char smem[];
    const uint32_t sb = s2u(smem);
    const int tid  = threadIdx.x;
    const int lane = tid & 31;
    const int wid  = tid >> 5;
    const int q0   = blockIdx.x << 7;
    const int h    = blockIdx.y;
    const int b    = blockIdx.z;
    const int kvh  = h >> 2;

    const __half* qhib = g_qhi + ((size_t)(b*NH_ + h)*S_ + q0)*D_;
    const __half* qlob = g_qlo + ((size_t)(b*NH_ + h)*S_ + q0)*D_;
    const __half* khb  = g_kh  + ((size_t)(b*NKV_ + kvh)*S_)*D_;
    const __half* vbb  = g_vh  + ((size_t)(b*NKV_ + kvh)*S_)*D_;

    #pragma unroll
    for (int j = 0; j < 4; ++j) {
        int u = tid + j * 256;              // 0..1023
        int r = u >> 3, c = u & 7;
        uint32_t so = (uint32_t)r * 128u + ((uint32_t)(c ^ (r & 7)) << 4);
        cp16(sb + so,          &qhib[(size_t)r * 64u + c * 8]);
        cp16(sb + 16384u + so, &qlob[(size_t)r * 64u + c * 8]);
    }
    fa_load_kv(khb, vbb, 0, sb, 0, tid);   // group: [Q + KV0]

    float oacc[8][4];
    #pragma unroll
    for (int dt = 0; dt < 8; ++dt)
        #pragma unroll
        for (int j = 0; j < 4; ++j) oacc[dt][j] = 0.f;
    float m0 = -INFINITY, m1 = -INFINITY, l0 = 0.f, l1 = 0.f;

    const int wrow = wid * 16;
    const uint32_t KH = sb + 32768u;

    for (int c = 0; c < 32; ++c) {
        const int buf = c & 1;
        if (c + 1 < 32) {
            fa_load_kv(khb, vbb, (c + 1) * 64, sb, buf ^ 1, tid);
            asm volatile("cp.async.wait_group 1;" ::: "memory");
        } else {
            asm volatile("cp.async.wait_group 0;" ::: "memory");
        }
        __syncthreads();

        const uint32_t kh = KH + (uint32_t)buf * FA_BUF;
        const uint32_t vv = kh + 8192u;

        float sacc[8][4];
        uint32_t shl[8][2];
        #pragma unroll
        for (int nt = 0; nt < 8; ++nt) {
            #pragma unroll
            for (int j = 0; j < 4; ++j) sacc[nt][j] = 0.f;
            shl[nt][0] = 0u; shl[nt][1] = 0u;
        }

        #pragma unroll
        for (int ks = 0; ks < 4; ++ks) {
            const int cg = ks * 2 + (lane >> 4);
            int rq = wrow + (lane & 15);
            uint32_t swq = (uint32_t)(cg ^ (rq & 7)) << 4;
            uint32_t aqh[4], aql[4];
            ldsm4(aqh, sb +          (uint32_t)rq * 128u + swq);
            ldsm4(aql, sb + 16384u + (uint32_t)rq * 128u + swq);
            uint32_t bh[8][2];
            #pragma unroll
            for (int kb = 0; kb < 4; ++kb) {
                int rk = kb * 16 + (lane & 15);
                uint32_t swk = (uint32_t)(cg ^ (rk & 7)) << 4;
                uint32_t t[4];
                ldsm4(t, kh + (uint32_t)rk * 128u + swk);
                bh[kb*2  ][0] = t[0]; bh[kb*2  ][1] = t[2];
                bh[kb*2+1][0] = t[1]; bh[kb*2+1][1] = t[3];
            }
            #pragma unroll
            for (int nt = 0; nt < 8; ++nt) mma16816h(sacc[nt], aqh, bh[nt]);
            #pragma unroll
            for (int nt = 0; nt < 8; ++nt) mma16816hacc(shl[nt], aql, bh[nt]);
        }
        #pragma unroll
        for (int nt = 0; nt < 8; ++nt) {
            __half2 p01 = *(__half2*)&shl[nt][0];
            __half2 p23 = *(__half2*)&shl[nt][1];
            sacc[nt][0] += __half2float(p01.x);
            sacc[nt][1] += __half2float(p01.y);
            sacc[nt][2] += __half2float(p23.x);
            sacc[nt][3] += __half2float(p23.y);
        }

        float mx0 = -INFINITY, mx1 = -INFINITY;
        #pragma unroll
        for (int nt = 0; nt < 8; ++nt) {
            #pragma unroll
            for (int j = 0; j < 4; ++j) sacc[nt][j] *= 0.125f;
            mx0 = fmaxf(mx0, fmaxf(sacc[nt][0], sacc[nt][1]));
            mx1 = fmaxf(mx1, fmaxf(sacc[nt][2], sacc[nt][3]));
        }
        #pragma unroll
        for (int off = 1; off < 4; off <<= 1) {
            mx0 = fmaxf(mx0, __shfl_xor_sync(0xffffffffu, mx0, off));
            mx1 = fmaxf(mx1, __shfl_xor_sync(0xffffffffu, mx1, off));
        }
        float mn0 = fmaxf(m0, mx0), mn1 = fmaxf(m1, mx1);
        float sc0 = __expf(m0 - mn0), sc1 = __expf(m1 - mn1);
        m0 = mn0; m1 = mn1;
        float rs0 = 0.f, rs1 = 0.f;
        #pragma unroll
        for (int nt = 0; nt < 8; ++nt) {
            sacc[nt][0] = __expf(sacc[nt][0] - mn0);
            sacc[nt][1] = __expf(sacc[nt][1] - mn0);
            sacc[nt][2] = __expf(sacc[nt][2] - mn1);
            sacc[nt][3] = __expf(sacc[nt][3] - mn1);
            rs0 += sacc[nt][0] + sacc[nt][1];
            rs1 += sacc[nt][2] + sacc[nt][3];
        }
        #pragma unroll
        for (int off = 1; off < 4; off <<= 1) {
            rs0 += __shfl_xor_sync(0xffffffffu, rs0, off);
            rs1 += __shfl_xor_sync(0xffffffffu, rs1, off);
        }
        l0 = l0 * sc0 + rs0;
        l1 = l1 * sc1 + rs1;
        #pragma unroll
        for (int dt = 0; dt < 8; ++dt) {
            oacc[dt][0] *= sc0; oacc[dt][1] *= sc0;
            oacc[dt][2] *= sc1; oacc[dt][3] *= sc1;
        }

        #pragma unroll
        for (int ks = 0; ks < 4; ++ks) {
            uint32_t pa[4];
            pa[0] = packf16(sacc[2*ks  ][0], sacc[2*ks  ][1]);
            pa[1] = packf16(sacc[2*ks  ][2], sacc[2*ks  ][3]);
            pa[2] = packf16(sacc[2*ks+1][0], sacc[2*ks+1][1]);
            pa[3] = packf16(sacc[2*ks+1][2], sacc[2*ks+1][3]);
            int rv = ks * 16 + (lane & 7) + ((lane >> 3) & 1) * 8;
            uint32_t rvb = vv + (uint32_t)rv * 128u;
            uint32_t bv[8][2];
            #pragma unroll
            for (int dp = 0; dp < 4; ++dp) {
                int cv = dp * 2 + (lane >> 4);
                uint32_t tv[4];
                ldsm4t(tv, rvb + ((uint32_t)(cv ^ (rv & 7)) << 4));
                bv[dp*2  ][0] = tv[0]; bv[dp*2  ][1] = tv[1];
                bv[dp*2+1][0] = tv[2]; bv[dp*2+1][1] = tv[3];
            }
            #pragma unroll
            for (int dt = 0; dt < 8; ++dt)
                mma16816h(oacc[dt], pa, bv[dt]);
        }
        __syncthreads();
    }

    float inv0 = 1.f / l0, inv1 = 1.f / l1;
    const int r0g = q0 + wrow + (lane >> 2);
    const size_t m0i = ((size_t)(b * S_ + r0g)) * 2048u + h * 64;
    const size_t m1i = m0i + 8u * 2048u;
    #pragma unroll
    for (int dt = 0; dt < 8; ++dt) {
        int d = dt * 8 + (lane & 3) * 2;
        float v0 = oacc[dt][0] * inv0, v1 = oacc[dt][1] * inv0;
        float v2 = oacc[dt][2] * inv1, v3 = oacc[dt][3] * inv1;
        __half2 h01 = mkh2(v0, v1), h23 = mkh2(v2, v3);
        *(__half2*)&g_aohi[m0i + d] = h01;
        *(__half2*)&g_aolo[m0i + d] =
            mkh2(v0 - __half2float(h01.x), v1 - __half2float(h01.y));
        *(__half2*)&g_aohi[m1i + d] = h23;
        *(__half2*)&g_aolo[m1i + d] =
            mkh2(v2 - __half2float(h23.x), v3 - __half2float(h23.y));
    }
}

// ---------------------------------------------------------------------------
extern "C" void kernel_launch(void* const* d_in, const int* in_sizes, int n_in,
                              void* d_out, int out_size)
{
    (void)in_sizes; (void)n_in; (void)out_size;
    const float* hs   = (const float*)d_in[0];
    const float* cosp = (const float*)d_in[1];
    const float* sinp = (const float*)d_in[2];
    const float* Wq = (const float*)d_in[4];
    const float* Wk = (const float*)d_in[5];
    const float* Wv = (const float*)d_in[6];
    const float* Wo = (const float*)d_in[7];
    float* out = (float*)d_out;

    __half *xhi, *xlo, *wh, *woh, *aohi, *aolo;
    cudaGetSymbolAddress((void**)&xhi,  g_xhi);  cudaGetSymbolAddress((void**)&xlo,  g_xlo);
    cudaGetSymbolAddress((void**)&wh,   g_wh);   cudaGetSymbolAddress((void**)&woh,  g_woh);
    cudaGetSymbolAddress((void**)&aohi, g_aohi); cudaGetSymbolAddress((void**)&aolo, g_aolo);

    const int T = 256;
    // 1) X -> fp16 hi/lo; all weights -> fp16 in one kernel
    split_f16<<<(4096*2048/2 + T-1)/T, T>>>(hs, xhi, xlo, 4096*2048/2);
    const int wtot = 2*WQ_F2 + 2*WK_F2;
    conv_w<<<(wtot + T-1)/T, T>>>(Wq, Wk, Wv, Wo, wh, woh);

    // 2) QKV projection with fused RoPE + fp16 epilogue
    const int gsmem = 2 * 24576;
    cudaFuncSetAttribute(gemm_mma, cudaFuncAttributeMaxDynamicSharedMemorySize, gsmem);
    dim3 g1(3072/128, 4096/128);
    gemm_mma<<<g1, 256, gsmem>>>(xhi, xlo, wh, cosp, sinp, 0, nullptr);

    // 3) Flash attention on tensor cores
    cudaFuncSetAttribute(flash_mma, cudaFuncAttributeMaxDynamicSharedMemorySize, FA_SMEM);
    dim3 g2(S_/128, NH_, B_);
    flash_mma<<<g2, 256, FA_SMEM>>>();

    // 4) O-projection
    dim3 g3(2048/128, 4096/128);
    gemm_mma<<<g3, 256, gsmem>>>(aohi, aolo, woh, nullptr, nullptr, 1, out);
}

// round 14
// speedup vs baseline: 1.0883x; 1.0281x over previous
#include <cuda_runtime.h>
#include <cuda_bf16.h>
#include <cuda_fp16.h>
#include <math.h>
#include <stdint.h>

#define B_   2
#define S_   2048
#define HID_ 2048
#define NH_  32
#define NKV_ 8
#define D_   64

// ---------------------------------------------------------------------------
// Device scratch (no allocations allowed)
// ---------------------------------------------------------------------------
__device__ __half g_qhi[B_*NH_ *S_*D_], g_qlo[B_*NH_ *S_*D_];  // Q fp16 hi/lo (post-RoPE)
__device__ __half g_kh [B_*NKV_*S_*D_];                        // K fp16 (post-RoPE)
__device__ __half g_vh [B_*NKV_*S_*D_];

__device__ __half g_xhi [4096*2048], g_xlo [4096*2048];   // X hi/lo (fp16)
__device__ __half g_wh  [3072*2048];                      // Wq|Wk|Wv fp16
__device__ __half g_woh [2048*2048];                      // Wo fp16
__device__ __half g_aohi[4096*2048], g_aolo[4096*2048];   // attention out hi/lo

// ---------------------------------------------------------------------------
// Baseline-PTX tensor helpers (NO tcgen05 — harness builds plain compute_103)
// ---------------------------------------------------------------------------
__device__ __forceinline__ uint32_t s2u(const void* p) {
    uint32_t a;
    asm("{ .reg .u64 t; cvta.to.shared.u64 t, %1; cvt.u32.u64 %0, t; }"
        : "=r"(a) : "l"(p));
    return a;
}
__device__ __forceinline__ void ldsm4(uint32_t* r, uint32_t addr) {
    asm volatile("ldmatrix.sync.aligned.m8n8.x4.shared.b16 {%0,%1,%2,%3}, [%4];"
        : "=r"(r[0]), "=r"(r[1]), "=r"(r[2]), "=r"(r[3]) : "r"(addr));
}
__device__ __forceinline__ void ldsm4t(uint32_t* r, uint32_t addr) {
    asm volatile("ldmatrix.sync.aligned.m8n8.x4.trans.shared.b16 {%0,%1,%2,%3}, [%4];"
        : "=r"(r[0]), "=r"(r[1]), "=r"(r[2]), "=r"(r[3]) : "r"(addr));
}
__device__ __forceinline__ void mma16816h(float* c, const uint32_t* a, const uint32_t* b) {
    asm volatile("mma.sync.aligned.m16n8k16.row.col.f32.f16.f16.f32 "
        "{%0,%1,%2,%3}, {%4,%5,%6,%7}, {%8,%9}, {%0,%1,%2,%3};"
        : "+f"(c[0]), "+f"(c[1]), "+f"(c[2]), "+f"(c[3])
        : "r"(a[0]), "r"(a[1]), "r"(a[2]), "r"(a[3]), "r"(b[0]), "r"(b[1]));
}
__device__ __forceinline__ void mma16816hacc(uint32_t* c, const uint32_t* a, const uint32_t* b) {
    asm volatile("mma.sync.aligned.m16n8k16.row.col.f16.f16.f16.f16 "
        "{%0,%1}, {%2,%3,%4,%5}, {%6,%7}, {%0,%1};"
        : "+r"(c[0]), "+r"(c[1])
        : "r"(a[0]), "r"(a[1]), "r"(a[2]), "r"(a[3]), "r"(b[0]), "r"(b[1]));
}
__device__ __forceinline__ void cp16(uint32_t saddr, const void* gaddr) {
    asm volatile("cp.async.cg.shared.global [%0], [%1], 16;"
                 :: "r"(saddr), "l"(gaddr));
}
__device__ __forceinline__ uint32_t packf16(float lo, float hi) {
    uint32_t d;
    asm("cvt.rn.f16x2.f32 %0, %1, %2;" : "=r"(d) : "f"(hi), "f"(lo));
    return d;
}
__device__ __forceinline__ __half2 mkh2(float a, float b) {
    __half2 h; h.x = __float2half(a); h.y = __float2half(b); return h;
}

// ---------------------------------------------------------------------------
// Prep kernels: X -> fp16 hi/lo split; all weights -> fp16 in ONE kernel.
// ---------------------------------------------------------------------------
__global__ void split_f16(const float* __restrict__ src,
                          __half* __restrict__ hi,
                          __half* __restrict__ lo, int n2)
{
    int i = blockIdx.x * blockDim.x + threadIdx.x;
    if (i >= n2) return;
    float2 v = ((const float2*)src)[i];
    __half h0 = __float2half(v.x);
    __half h1 = __float2half(v.y);
    __half2 hh; hh.x = h0; hh.y = h1;
    __half2 ll; ll.x = __float2half(v.x - __half2float(h0));
    ll.y = __float2half(v.y - __half2float(h1));
    ((__half2*)hi)[i] = hh;
    ((__half2*)lo)[i] = ll;
}

#define WQ_F2 (2048*2048/2)
#define WK_F2 ( 512*2048/2)
__global__ void conv_w(const float* __restrict__ Wq, const float* __restrict__ Wk,
                       const float* __restrict__ Wv, const float* __restrict__ Wo,
                       __half* __restrict__ wh, __half* __restrict__ woh)
{
    int i = blockIdx.x * blockDim.x + threadIdx.x;   // float2 index
    const float2* src; __half* dst; int j;
    if (i < WQ_F2)                        { src = (const float2*)Wq; dst = wh;                  j = i; }
    else if (i < WQ_F2 + WK_F2)           { src = (const float2*)Wk; dst = wh + 2048*2048;      j = i - WQ_F2; }
    else if (i < WQ_F2 + 2*WK_F2)         { src = (const float2*)Wv; dst = wh + 2560*2048;      j = i - WQ_F2 - WK_F2; }
    else if (i < 2*WQ_F2 + 2*WK_F2)       { src = (const float2*)Wo; dst = woh;                 j = i - WQ_F2 - 2*WK_F2; }
    else return;
    float2 v = src[j];
    __half2 h; h.x = __float2half(v.x); h.y = __float2half(v.y);
    ((__half2*)dst)[j] = h;
}

// ---------------------------------------------------------------------------
// fp32-emulated GEMM on fp16 mma.sync, 2 MMAs/k-step (128x128, occ 2):
//   C = (A_hi + A_lo) * fp16(B)
// mode 0: epilogue applies RoPE (fp32) and writes qhi/qlo, kh, vh fp16 directly.
// mode 1: writes fp32 outp.
// ---------------------------------------------------------------------------
#define NCHUNK 64      // 2048 / 32

__device__ __forceinline__ void load_chunk(
    const __half* __restrict__ Ahi, const __half* __restrict__ Alo,
    const __half* __restrict__ Bh,
    int m0, int n0, uint32_t sb, int buf, int chunk, int tid)
{
    const __half* srcs[3] = {Ahi, Alo, Bh};
    const int r0s[3] = {m0, m0, n0};
    #pragma unroll
    for (int op = 0; op < 3; ++op) {
        #pragma unroll
        for (int j = 0; j < 2; ++j) {
            int u = tid + j * 256;
            int r = u >> 2, c = u & 3;
            const __half* g =
                srcs[op] + (size_t)(r0s[op] + r) * 2048u + chunk * 32 + c * 8;
            uint32_t so = sb + (uint32_t)buf * 24576u + (uint32_t)op * 8192u
                        + (uint32_t)r * 64u
                        + ((uint32_t)(c ^ ((r >> 1) & 3)) << 4);
            cp16(so, g);
        }
    }
    asm volatile("cp.async.commit_group;" ::: "memory");
}

__global__ __launch_bounds__(256, 2) void gemm_mma(
    const __half* __restrict__ Ahi, const __half* __restrict__ Alo,
    const __half* __restrict__ Bh,
    const float* __restrict__ cosp, const float* __restrict__ sinp,
    int mode, float* __restrict__ outp)
{
    extern __shared__ char smem[];
    const uint32_t sb = s2u(smem);
    const int tid  = threadIdx.x;
    const int lane = tid & 31;
    const int wid  = tid >> 5;
    const int wm   = wid & 3;
    const int wn   = wid >> 2;
    const int m0   = blockIdx.y << 7;
    const int n0   = blockIdx.x << 7;

    float acc[2][8][4];
    #pragma unroll
    for (int mt = 0; mt < 2; ++mt)
        #pragma unroll
        for (int nt = 0; nt < 8; ++nt)
            #pragma unroll
            for (int j = 0; j < 4; ++j) acc[mt][nt][j] = 0.f;

    load_chunk(Ahi, Alo, Bh, m0, n0, sb, 0, 0, tid);

    for (int c = 0; c < NCHUNK; ++c) {
        const int buf = c & 1;
        if (c + 1 < NCHUNK) {
            load_chunk(Ahi, Alo, Bh, m0, n0, sb, buf ^ 1, c + 1, tid);
            asm volatile("cp.async.wait_group 1;" ::: "memory");
        } else {
            asm volatile("cp.async.wait_group 0;" ::: "memory");
        }
        __syncthreads();

        const uint32_t base = sb + (uint32_t)buf * 24576u;
        #pragma unroll
        for (int ks = 0; ks < 2; ++ks) {
            const int cg = ks * 2 + (lane >> 4);
            uint32_t ah[2][4], al[2][4];
            #pragma unroll
            for (int mt = 0; mt < 2; ++mt) {
                int r = wm * 32 + mt * 16 + (lane & 15);
                uint32_t sw = (uint32_t)(cg ^ ((r >> 1) & 3)) << 4;
                ldsm4(ah[mt], base +     0u + (uint32_t)r * 64u + sw);
                ldsm4(al[mt], base + 8192u + (uint32_t)r * 64u + sw);
            }
            uint32_t bh[8][2];
            #pragma unroll
            for (int nt2 = 0; nt2 < 4; ++nt2) {
                int r = wn * 64 + nt2 * 16 + (lane & 15);
                uint32_t sw = (uint32_t)(cg ^ ((r >> 1) & 3)) << 4;
                uint32_t t[4];
                ldsm4(t, base + 16384u + (uint32_t)r * 64u + sw);
                bh[nt2*2  ][0] = t[0]; bh[nt2*2  ][1] = t[2];
                bh[nt2*2+1][0] = t[1]; bh[nt2*2+1][1] = t[3];
            }
            #pragma unroll
            for (int mt = 0; mt < 2; ++mt)
                #pragma unroll
                for (int nt = 0; nt < 8; ++nt) {
                    mma16816h(acc[mt][nt], ah[mt], bh[nt]);
                    mma16816h(acc[mt][nt], al[mt], bh[nt]);
                }
        }
        __syncthreads();
    }

    if (mode == 1) {
        #pragma unroll
        for (int mt = 0; mt < 2; ++mt)
            #pragma unroll
            for (int half = 0; half < 2; ++half) {
                const int m = m0 + wm * 32 + mt * 16 + (lane >> 2) + half * 8;
                #pragma unroll
                for (int nt = 0; nt < 8; ++nt) {
                    const int n = n0 + wn * 64 + nt * 8 + (lane & 3) * 2;
                    *(float2*)&outp[(size_t)m * 2048 + n] =
                        make_float2(acc[mt][nt][half*2], acc[mt][nt][half*2+1]);
                }
            }
        return;
    }

    // mode 0: fused RoPE (Q/K) + fp16 conversion.
    #pragma unroll
    for (int mt = 0; mt < 2; ++mt) {
        #pragma unroll
        for (int half = 0; half < 2; ++half) {
            const int m  = m0 + wm * 32 + mt * 16 + (lane >> 2) + half * 8;
            const int bb = m >> 11;
            const int s  = m & 2047;
            const size_t cb = ((size_t)bb * S_ + s) * D_;
            #pragma unroll
            for (int ntp = 0; ntp < 4; ++ntp) {
                const int n = n0 + wn * 64 + ntp * 8 + (lane & 3) * 2;
                float x1a = acc[mt][ntp  ][half*2], x1b = acc[mt][ntp  ][half*2+1];
                float x2a = acc[mt][ntp+4][half*2], x2b = acc[mt][ntp+4][half*2+1];
                if (n < 2560) {
                    const int nn = (n < 2048) ? n : n - 2048;
                    const int h = nn >> 6, d = nn & 63;
                    float2 c1 = *(const float2*)&cosp[cb + d];
                    float2 c2 = *(const float2*)&cosp[cb + d + 32];
                    float2 s1 = *(const float2*)&sinp[cb + d];
                    float2 s2 = *(const float2*)&sinp[cb + d + 32];
                    float y1a = x1a*c1.x - x2a*s1.x;
                    float y1b = x1b*c1.y - x2b*s1.y;
                    float y2a = x2a*c2.x + x1a*s2.x;
                    float y2b = x2b*c2.y + x1b*s2.y;
                    if (n < 2048) {
                        const size_t base = (((size_t)bb*NH_ + h)*S_ + s)*D_ + d;
                        __half2 h1 = mkh2(y1a, y1b), h2v = mkh2(y2a, y2b);
                        *(__half2*)&g_qhi[base]      = h1;
                        *(__half2*)&g_qhi[base + 32] = h2v;
                        *(__half2*)&g_qlo[base] =
                            mkh2(y1a - __half2float(h1.x),  y1b - __half2float(h1.y));
                        *(__half2*)&g_qlo[base + 32] =
                            mkh2(y2a - __half2float(h2v.x), y2b - __half2float(h2v.y));
                    } else {
                        const size_t base = (((size_t)bb*NKV_ + h)*S_ + s)*D_ + d;
                        *(__half2*)&g_kh[base]      = mkh2(y1a, y1b);
                        *(__half2*)&g_kh[base + 32] = mkh2(y2a, y2b);
                    }
                } else {
                    const int nn = n - 2560;
                    const int h = nn >> 6, d = nn & 63;
                    const size_t base = (((size_t)bb*NKV_ + h)*S_ + s)*D_ + d;
                    *(__half2*)&g_vh[base]      = mkh2(x1a, x1b);
                    *(__half2*)&g_vh[base + 32] = mkh2(x2a, x2b);
                }
            }
        }
    }
}

// ---------------------------------------------------------------------------
// Flash attention on mma.sync.  Same algorithm as R13 (rel_err 8.778e-4);
// __launch_bounds__(256, 2) forces 128-reg cap -> 2 CTAs/SM (16 warps/SM).
// smem 64KB/CTA -> 128KB/SM.  Minor register spills traded for 2x issue slots.
// ---------------------------------------------------------------------------
#define FA_BUF  16384u
#define FA_SMEM (32768 + 2*16384)

__device__ __forceinline__ void fa_load_kv(const __half* kh, const __half* vb,
                                           int k0, uint32_t sb, int buf, int tid)
{
    #pragma unroll
    for (int j = 0; j < 2; ++j) {
        int u = tid + j * 256;          // 0..511
        int r = u >> 3, c = u & 7;
        uint32_t so = sb + 32768u + (uint32_t)buf * FA_BUF
                    + (uint32_t)r * 128u + ((uint32_t)(c ^ (r & 7)) << 4);
        cp16(so,         &kh[(size_t)(k0 + r) * 64u + c * 8]);
        cp16(so + 8192u, &vb[(size_t)(k0 + r) * 64u + c * 8]);
    }
    asm volatile("cp.async.commit_group;" ::: "memory");
}

__global__ __launch_bounds__(256, 2) void flash_mma()
{
    extern __shared__ char smem[];
    const uint32_t sb = s2u(smem);
    const int tid  = threadIdx.x;
    const int lane = tid & 31;
    const int wid  = tid >> 5;
    const int q0   = blockIdx.x << 7;
    const int h    = blockIdx.y;
    const int b    = blockIdx.z;
    const int kvh  = h >> 2;

    const __half* qhib = g_qhi + ((size_t)(b*NH_ + h)*S_ + q0)*D_;
    const __half* qlob = g_qlo + ((size_t)(b*NH_ + h)*S_ + q0)*D_;
    const __half* khb  = g_kh  + ((size_t)(b*NKV_ + kvh)*S_)*D_;
    const __half* vbb  = g_vh  + ((size_t)(b*NKV_ + kvh)*S_)*D_;

    #pragma unroll
    for (int j = 0; j < 4; ++j) {
        int u = tid + j * 256;              // 0..1023
        int r = u >> 3, c = u & 7;
        uint32_t so = (uint32_t)r * 128u + ((uint32_t)(c ^ (r & 7)) << 4);
        cp16(sb + so,          &qhib[(size_t)r * 64u + c * 8]);
        cp16(sb + 16384u + so, &qlob[(size_t)r * 64u + c * 8]);
    }
    fa_load_kv(khb, vbb, 0, sb, 0, tid);   // group: [Q + KV0]

    float oacc[8][4];
    #pragma unroll
    for (int dt = 0; dt < 8; ++dt)
        #pragma unroll
        for (int j = 0; j < 4; ++j) oacc[dt][j] = 0.f;
    float m0 = -INFINITY, m1 = -INFINITY, l0 = 0.f, l1 = 0.f;

    const int wrow = wid * 16;
    const uint32_t KH = sb + 32768u;

    for (int c = 0; c < 32; ++c) {
        const int buf = c & 1;
        if (c + 1 < 32) {
            fa_load_kv(khb, vbb, (c + 1) * 64, sb, buf ^ 1, tid);
            asm volatile("cp.async.wait_group 1;" ::: "memory");
        } else {
            asm volatile("cp.async.wait_group 0;" ::: "memory");
        }
        __syncthreads();

        const uint32_t kh = KH + (uint32_t)buf * FA_BUF;
        const uint32_t vv = kh + 8192u;

        float sacc[8][4];
        uint32_t shl[8][2];
        #pragma unroll
        for (int nt = 0; nt < 8; ++nt) {
            #pragma unroll
            for (int j = 0; j < 4; ++j) sacc[nt][j] = 0.f;
            shl[nt][0] = 0u; shl[nt][1] = 0u;
        }

        #pragma unroll
        for (int ks = 0; ks < 4; ++ks) {
            const int cg = ks * 2 + (lane >> 4);
            int rq = wrow + (lane & 15);
            uint32_t swq = (uint32_t)(cg ^ (rq & 7)) << 4;
            uint32_t aqh[4], aql[4];
            ldsm4(aqh, sb +          (uint32_t)rq * 128u + swq);
            ldsm4(aql, sb + 16384u + (uint32_t)rq * 128u + swq);
            uint32_t bh[8][2];
            #pragma unroll
            for (int kb = 0; kb < 4; ++kb) {
                int rk = kb * 16 + (lane & 15);
                uint32_t swk = (uint32_t)(cg ^ (rk & 7)) << 4;
                uint32_t t[4];
                ldsm4(t, kh + (uint32_t)rk * 128u + swk);
                bh[kb*2  ][0] = t[0]; bh[kb*2  ][1] = t[2];
                bh[kb*2+1][0] = t[1]; bh[kb*2+1][1] = t[3];
            }
            #pragma unroll
            for (int nt = 0; nt < 8; ++nt) mma16816h(sacc[nt], aqh, bh[nt]);
            #pragma unroll
            for (int nt = 0; nt < 8; ++nt) mma16816hacc(shl[nt], aql, bh[nt]);
        }
        #pragma unroll
        for (int nt = 0; nt < 8; ++nt) {
            __half2 p01 = *(__half2*)&shl[nt][0];
            __half2 p23 = *(__half2*)&shl[nt][1];
            sacc[nt][0] += __half2float(p01.x);
            sacc[nt][1] += __half2float(p01.y);
            sacc[nt][2] += __half2float(p23.x);
            sacc[nt][3] += __half2float(p23.y);
        }

        float mx0 = -INFINITY, mx1 = -INFINITY;
        #pragma unroll
        for (int nt = 0; nt < 8; ++nt) {
            #pragma unroll
            for (int j = 0; j < 4; ++j) sacc[nt][j] *= 0.125f;
            mx0 = fmaxf(mx0, fmaxf(sacc[nt][0], sacc[nt][1]));
            mx1 = fmaxf(mx1, fmaxf(sacc[nt][2], sacc[nt][3]));
        }
        #pragma unroll
        for (int off = 1; off < 4; off <<= 1) {
            mx0 = fmaxf(mx0, __shfl_xor_sync(0xffffffffu, mx0, off));
            mx1 = fmaxf(mx1, __shfl_xor_sync(0xffffffffu, mx1, off));
        }
        float mn0 = fmaxf(m0, mx0), mn1 = fmaxf(m1, mx1);
        float sc0 = __expf(m0 - mn0), sc1 = __expf(m1 - mn1);
        m0 = mn0; m1 = mn1;
        float rs0 = 0.f, rs1 = 0.f;
        #pragma unroll
        for (int nt = 0; nt < 8; ++nt) {
            sacc[nt][0] = __expf(sacc[nt][0] - mn0);
            sacc[nt][1] = __expf(sacc[nt][1] - mn0);
            sacc[nt][2] = __expf(sacc[nt][2] - mn1);
            sacc[nt][3] = __expf(sacc[nt][3] - mn1);
            rs0 += sacc[nt][0] + sacc[nt][1];
            rs1 += sacc[nt][2] + sacc[nt][3];
        }
        #pragma unroll
        for (int off = 1; off < 4; off <<= 1) {
            rs0 += __shfl_xor_sync(0xffffffffu, rs0, off);
            rs1 += __shfl_xor_sync(0xffffffffu, rs1, off);
        }
        l0 = l0 * sc0 + rs0;
        l1 = l1 * sc1 + rs1;
        #pragma unroll
        for (int dt = 0; dt < 8; ++dt) {
            oacc[dt][0] *= sc0; oacc[dt][1] *= sc0;
            oacc[dt][2] *= sc1; oacc[dt][3] *= sc1;
        }

        #pragma unroll
        for (int ks = 0; ks < 4; ++ks) {
            uint32_t pa[4];
            pa[0] = packf16(sacc[2*ks  ][0], sacc[2*ks  ][1]);
            pa[1] = packf16(sacc[2*ks  ][2], sacc[2*ks  ][3]);
            pa[2] = packf16(sacc[2*ks+1][0], sacc[2*ks+1][1]);
            pa[3] = packf16(sacc[2*ks+1][2], sacc[2*ks+1][3]);
            int rv = ks * 16 + (lane & 7) + ((lane >> 3) & 1) * 8;
            uint32_t rvb = vv + (uint32_t)rv * 128u;
            uint32_t bv[8][2];
            #pragma unroll
            for (int dp = 0; dp < 4; ++dp) {
                int cv = dp * 2 + (lane >> 4);
                uint32_t tv[4];
                ldsm4t(tv, rvb + ((uint32_t)(cv ^ (rv & 7)) << 4));
                bv[dp*2  ][0] = tv[0]; bv[dp*2  ][1] = tv[1];
                bv[dp*2+1][0] = tv[2]; bv[dp*2+1][1] = tv[3];
            }
            #pragma unroll
            for (int dt = 0; dt < 8; ++dt)
                mma16816h(oacc[dt], pa, bv[dt]);
        }
        __syncthreads();
    }

    float inv0 = 1.f / l0, inv1 = 1.f / l1;
    const int r0g = q0 + wrow + (lane >> 2);
    const size_t m0i = ((size_t)(b * S_ + r0g)) * 2048u + h * 64;
    const size_t m1i = m0i + 8u * 2048u;
    #pragma unroll
    for (int dt = 0; dt < 8; ++dt) {
        int d = dt * 8 + (lane & 3) * 2;
        float v0 = oacc[dt][0] * inv0, v1 = oacc[dt][1] * inv0;
        float v2 = oacc[dt][2] * inv1, v3 = oacc[dt][3] * inv1;
        __half2 h01 = mkh2(v0, v1), h23 = mkh2(v2, v3);
        *(__half2*)&g_aohi[m0i + d] = h01;
        *(__half2*)&g_aolo[m0i + d] =
            mkh2(v0 - __half2float(h01.x), v1 - __half2float(h01.y));
        *(__half2*)&g_aohi[m1i + d] = h23;
        *(__half2*)&g_aolo[m1i + d] =
            mkh2(v2 - __half2float(h23.x), v3 - __half2float(h23.y));
    }
}

// ---------------------------------------------------------------------------
extern "C" void kernel_launch(void* const* d_in, const int* in_sizes, int n_in,
                              void* d_out, int out_size)
{
    (void)in_sizes; (void)n_in; (void)out_size;
    const float* hs   = (const float*)d_in[0];
    const float* cosp = (const float*)d_in[1];
    const float* sinp = (const float*)d_in[2];
    const float* Wq = (const float*)d_in[4];
    const float* Wk = (const float*)d_in[5];
    const float* Wv = (const float*)d_in[6];
    const float* Wo = (const float*)d_in[7];
    float* out = (float*)d_out;

    __half *xhi, *xlo, *wh, *woh, *aohi, *aolo;
    cudaGetSymbolAddress((void**)&xhi,  g_xhi);  cudaGetSymbolAddress((void**)&xlo,  g_xlo);
    cudaGetSymbolAddress((void**)&wh,   g_wh);   cudaGetSymbolAddress((void**)&woh,  g_woh);
    cudaGetSymbolAddress((void**)&aohi, g_aohi); cudaGetSymbolAddress((void**)&aolo, g_aolo);

    const int T = 256;
    // 1) X -> fp16 hi/lo; all weights -> fp16 in one kernel
    split_f16<<<(4096*2048/2 + T-1)/T, T>>>(hs, xhi, xlo, 4096*2048/2);
    const int wtot = 2*WQ_F2 + 2*WK_F2;
    conv_w<<<(wtot + T-1)/T, T>>>(Wq, Wk, Wv, Wo, wh, woh);

    // 2) QKV projection with fused RoPE + fp16 epilogue
    const int gsmem = 2 * 24576;
    cudaFuncSetAttribute(gemm_mma, cudaFuncAttributeMaxDynamicSharedMemorySize, gsmem);
    dim3 g1(3072/128, 4096/128);
    gemm_mma<<<g1, 256, gsmem>>>(xhi, xlo, wh, cosp, sinp, 0, nullptr);

    // 3) Flash attention on tensor cores (occ 2)
    cudaFuncSetAttribute(flash_mma, cudaFuncAttributeMaxDynamicSharedMemorySize, FA_SMEM);
    dim3 g2(S_/128, NH_, B_);
    flash_mma<<<g2, 256, FA_SMEM>>>();

    // 4) O-projection
    dim3 g3(2048/128, 4096/128);
    gemm_mma<<<g3, 256, gsmem>>>(aohi, aolo, woh, nullptr, nullptr, 1, out);
}

// round 15
// speedup vs baseline: 1.1484x; 1.0552x over previous
#include <cuda_runtime.h>
#include <cuda_bf16.h>
#include <cuda_fp16.h>
#include <math.h>
#include <stdint.h>

#define B_   2
#define S_   2048
#define HID_ 2048
#define NH_  32
#define NKV_ 8
#define D_   64

// ---------------------------------------------------------------------------
// Device scratch (no allocations allowed)
// ---------------------------------------------------------------------------
__device__ __half g_qhi[B_*NH_ *S_*D_], g_qlo[B_*NH_ *S_*D_];  // Q fp16 hi/lo (post-RoPE)
__device__ __half g_kh [B_*NKV_*S_*D_];                        // K fp16 (post-RoPE)
__device__ __half g_vh [B_*NKV_*S_*D_];

__device__ __half g_xhi [4096*2048], g_xlo [4096*2048];   // X hi/lo (fp16)
__device__ __half g_wh  [3072*2048];                      // Wq|Wk|Wv fp16
__device__ __half g_woh [2048*2048];                      // Wo fp16
__device__ __half g_aohi[4096*2048], g_aolo[4096*2048];   // attention out hi/lo

// ---------------------------------------------------------------------------
// Baseline-PTX tensor helpers (NO tcgen05 — harness builds plain compute_103)
// ---------------------------------------------------------------------------
__device__ __forceinline__ uint32_t s2u(const void* p) {
    uint32_t a;
    asm("{ .reg .u64 t; cvta.to.shared.u64 t, %1; cvt.u32.u64 %0, t; }"
        : "=r"(a) : "l"(p));
    return a;
}
__device__ __forceinline__ void ldsm4(uint32_t* r, uint32_t addr) {
    asm volatile("ldmatrix.sync.aligned.m8n8.x4.shared.b16 {%0,%1,%2,%3}, [%4];"
        : "=r"(r[0]), "=r"(r[1]), "=r"(r[2]), "=r"(r[3]) : "r"(addr));
}
__device__ __forceinline__ void ldsm4t(uint32_t* r, uint32_t addr) {
    asm volatile("ldmatrix.sync.aligned.m8n8.x4.trans.shared.b16 {%0,%1,%2,%3}, [%4];"
        : "=r"(r[0]), "=r"(r[1]), "=r"(r[2]), "=r"(r[3]) : "r"(addr));
}
__device__ __forceinline__ void mma16816h(float* c, const uint32_t* a, const uint32_t* b) {
    asm volatile("mma.sync.aligned.m16n8k16.row.col.f32.f16.f16.f32 "
        "{%0,%1,%2,%3}, {%4,%5,%6,%7}, {%8,%9}, {%0,%1,%2,%3};"
        : "+f"(c[0]), "+f"(c[1]), "+f"(c[2]), "+f"(c[3])
        : "r"(a[0]), "r"(a[1]), "r"(a[2]), "r"(a[3]), "r"(b[0]), "r"(b[1]));
}
__device__ __forceinline__ void mma16816hacc(uint32_t* c, const uint32_t* a, const uint32_t* b) {
    asm volatile("mma.sync.aligned.m16n8k16.row.col.f16.f16.f16.f16 "
        "{%0,%1}, {%2,%3,%4,%5}, {%6,%7}, {%0,%1};"
        : "+r"(c[0]), "+r"(c[1])
        : "r"(a[0]), "r"(a[1]), "r"(a[2]), "r"(a[3]), "r"(b[0]), "r"(b[1]));
}
__device__ __forceinline__ void cp16(uint32_t saddr, const void* gaddr) {
    asm volatile("cp.async.cg.shared.global [%0], [%1], 16;"
                 :: "r"(saddr), "l"(gaddr));
}
__device__ __forceinline__ uint32_t packf16(float lo, float hi) {
    uint32_t d;
    asm("cvt.rn.f16x2.f32 %0, %1, %2;" : "=r"(d) : "f"(hi), "f"(lo));
    return d;
}
__device__ __forceinline__ __half2 mkh2(float a, float b) {
    __half2 h; h.x = __float2half(a); h.y = __float2half(b); return h;
}

// ---------------------------------------------------------------------------
// Prep: X -> fp16 hi/lo split AND all weights -> fp16, one kernel.
// ---------------------------------------------------------------------------
#define X_F2  (4096*2048/2)
#define WQ_F2 (2048*2048/2)
#define WK_F2 ( 512*2048/2)
#define PREP_TOT (X_F2 + 2*WQ_F2 + 2*WK_F2)

__global__ void prep_all(const float* __restrict__ hs,
                         const float* __restrict__ Wq, const float* __restrict__ Wk,
                         const float* __restrict__ Wv, const float* __restrict__ Wo,
                         __half* __restrict__ xhi, __half* __restrict__ xlo,
                         __half* __restrict__ wh,  __half* __restrict__ woh)
{
    int i = blockIdx.x * blockDim.x + threadIdx.x;
    if (i < X_F2) {
        float2 v = ((const float2*)hs)[i];
        __half h0 = __float2half(v.x);
        __half h1 = __float2half(v.y);
        __half2 hh; hh.x = h0; hh.y = h1;
        __half2 ll; ll.x = __float2half(v.x - __half2float(h0));
        ll.y = __float2half(v.y - __half2float(h1));
        ((__half2*)xhi)[i] = hh;
        ((__half2*)xlo)[i] = ll;
        return;
    }
    int k = i - X_F2;
    const float2* src; __half* dst; int j;
    if (k < WQ_F2)                  { src = (const float2*)Wq; dst = wh;             j = k; }
    else if (k < WQ_F2 + WK_F2)     { src = (const float2*)Wk; dst = wh + 2048*2048; j = k - WQ_F2; }
    else if (k < WQ_F2 + 2*WK_F2)   { src = (const float2*)Wv; dst = wh + 2560*2048; j = k - WQ_F2 - WK_F2; }
    else if (k < 2*WQ_F2 + 2*WK_F2) { src = (const float2*)Wo; dst = woh;            j = k - WQ_F2 - 2*WK_F2; }
    else return;
    float2 v = src[j];
    __half2 h; h.x = __float2half(v.x); h.y = __float2half(v.y);
    ((__half2*)dst)[j] = h;
}

// ---------------------------------------------------------------------------
// fp32-emulated GEMM on fp16 mma.sync, 2 MMAs/k-step (128x128, occ 2):
//   C = (A_hi + A_lo) * fp16(B)
// Single __syncthreads per chunk: wait(c) -> sync -> prefetch(c+1) -> compute(c).
// mode 0: fused RoPE + fp16 q/k/v epilogue; mode 1: fp32 outp.
// ---------------------------------------------------------------------------
#define NCHUNK 64      // 2048 / 32

__device__ __forceinline__ void load_chunk(
    const __half* __restrict__ Ahi, const __half* __restrict__ Alo,
    const __half* __restrict__ Bh,
    int m0, int n0, uint32_t sb, int buf, int chunk, int tid)
{
    const __half* srcs[3] = {Ahi, Alo, Bh};
    const int r0s[3] = {m0, m0, n0};
    #pragma unroll
    for (int op = 0; op < 3; ++op) {
        #pragma unroll
        for (int j = 0; j < 2; ++j) {
            int u = tid + j * 256;
            int r = u >> 2, c = u & 3;
            const __half* g =
                srcs[op] + (size_t)(r0s[op] + r) * 2048u + chunk * 32 + c * 8;
            uint32_t so = sb + (uint32_t)buf * 24576u + (uint32_t)op * 8192u
                        + (uint32_t)r * 64u
                        + ((uint32_t)(c ^ ((r >> 1) & 3)) << 4);
            cp16(so, g);
        }
    }
    asm volatile("cp.async.commit_group;" ::: "memory");
}

__global__ __launch_bounds__(256, 2) void gemm_mma(
    const __half* __restrict__ Ahi, const __half* __restrict__ Alo,
    const __half* __restrict__ Bh,
    const float* __restrict__ cosp, const float* __restrict__ sinp,
    int mode, float* __restrict__ outp)
{
    extern __shared__ char smem[];
    const uint32_t sb = s2u(smem);
    const int tid  = threadIdx.x;
    const int lane = tid & 31;
    const int wid  = tid >> 5;
    const int wm   = wid & 3;
    const int wn   = wid >> 2;
    const int m0   = blockIdx.y << 7;
    const int n0   = blockIdx.x << 7;

    float acc[2][8][4];
    #pragma unroll
    for (int mt = 0; mt < 2; ++mt)
        #pragma unroll
        for (int nt = 0; nt < 8; ++nt)
            #pragma unroll
            for (int j = 0; j < 4; ++j) acc[mt][nt][j] = 0.f;

    load_chunk(Ahi, Alo, Bh, m0, n0, sb, 0, 0, tid);

    for (int c = 0; c < NCHUNK; ++c) {
        const int buf = c & 1;
        asm volatile("cp.async.wait_group 0;" ::: "memory");   // chunk c complete
        __syncthreads();                                       // all warps done with c-1
        if (c + 1 < NCHUNK)
            load_chunk(Ahi, Alo, Bh, m0, n0, sb, buf ^ 1, c + 1, tid);

        const uint32_t base = sb + (uint32_t)buf * 24576u;
        #pragma unroll
        for (int ks = 0; ks < 2; ++ks) {
            const int cg = ks * 2 + (lane >> 4);
            uint32_t ah[2][4], al[2][4];
            #pragma unroll
            for (int mt = 0; mt < 2; ++mt) {
                int r = wm * 32 + mt * 16 + (lane & 15);
                uint32_t sw = (uint32_t)(cg ^ ((r >> 1) & 3)) << 4;
                ldsm4(ah[mt], base +     0u + (uint32_t)r * 64u + sw);
                ldsm4(al[mt], base + 8192u + (uint32_t)r * 64u + sw);
            }
            uint32_t bh[8][2];
            #pragma unroll
            for (int nt2 = 0; nt2 < 4; ++nt2) {
                int r = wn * 64 + nt2 * 16 + (lane & 15);
                uint32_t sw = (uint32_t)(cg ^ ((r >> 1) & 3)) << 4;
                uint32_t t[4];
                ldsm4(t, base + 16384u + (uint32_t)r * 64u + sw);
                bh[nt2*2  ][0] = t[0]; bh[nt2*2  ][1] = t[2];
                bh[nt2*2+1][0] = t[1]; bh[nt2*2+1][1] = t[3];
            }
            #pragma unroll
            for (int mt = 0; mt < 2; ++mt)
                #pragma unroll
                for (int nt = 0; nt < 8; ++nt) {
                    mma16816h(acc[mt][nt], ah[mt], bh[nt]);
                    mma16816h(acc[mt][nt], al[mt], bh[nt]);
                }
        }
    }

    if (mode == 1) {
        #pragma unroll
        for (int mt = 0; mt < 2; ++mt)
            #pragma unroll
            for (int half = 0; half < 2; ++half) {
                const int m = m0 + wm * 32 + mt * 16 + (lane >> 2) + half * 8;
                #pragma unroll
                for (int nt = 0; nt < 8; ++nt) {
                    const int n = n0 + wn * 64 + nt * 8 + (lane & 3) * 2;
                    *(float2*)&outp[(size_t)m * 2048 + n] =
                        make_float2(acc[mt][nt][half*2], acc[mt][nt][half*2+1]);
                }
            }
        return;
    }

    // mode 0: fused RoPE (Q/K) + fp16 conversion.
    #pragma unroll
    for (int mt = 0; mt < 2; ++mt) {
        #pragma unroll
        for (int half = 0; half < 2; ++half) {
            const int m  = m0 + wm * 32 + mt * 16 + (lane >> 2) + half * 8;
            const int bb = m >> 11;
            const int s  = m & 2047;
            const size_t cb = ((size_t)bb * S_ + s) * D_;
            #pragma unroll
            for (int ntp = 0; ntp < 4; ++ntp) {
                const int n = n0 + wn * 64 + ntp * 8 + (lane & 3) * 2;
                float x1a = acc[mt][ntp  ][half*2], x1b = acc[mt][ntp  ][half*2+1];
                float x2a = acc[mt][ntp+4][half*2], x2b = acc[mt][ntp+4][half*2+1];
                if (n < 2560) {
                    const int nn = (n < 2048) ? n : n - 2048;
                    const int h = nn >> 6, d = nn & 63;
                    float2 c1 = *(const float2*)&cosp[cb + d];
                    float2 c2 = *(const float2*)&cosp[cb + d + 32];
                    float2 s1 = *(const float2*)&sinp[cb + d];
                    float2 s2 = *(const float2*)&sinp[cb + d + 32];
                    float y1a = x1a*c1.x - x2a*s1.x;
                    float y1b = x1b*c1.y - x2b*s1.y;
                    float y2a = x2a*c2.x + x1a*s2.x;
                    float y2b = x2b*c2.y + x1b*s2.y;
                    if (n < 2048) {
                        const size_t base = (((size_t)bb*NH_ + h)*S_ + s)*D_ + d;
                        __half2 h1 = mkh2(y1a, y1b), h2v = mkh2(y2a, y2b);
                        *(__half2*)&g_qhi[base]      = h1;
                        *(__half2*)&g_qhi[base + 32] = h2v;
                        *(__half2*)&g_qlo[base] =
                            mkh2(y1a - __half2float(h1.x),  y1b - __half2float(h1.y));
                        *(__half2*)&g_qlo[base + 32] =
                            mkh2(y2a - __half2float(h2v.x), y2b - __half2float(h2v.y));
                    } else {
                        const size_t base = (((size_t)bb*NKV_ + h)*S_ + s)*D_ + d;
                        *(__half2*)&g_kh[base]      = mkh2(y1a, y1b);
                        *(__half2*)&g_kh[base + 32] = mkh2(y2a, y2b);
                    }
                } else {
                    const int nn = n - 2560;
                    const int h = nn >> 6, d = nn & 63;
                    const size_t base = (((size_t)bb*NKV_ + h)*S_ + s)*D_ + d;
                    *(__half2*)&g_vh[base]      = mkh2(x1a, x1b);
                    *(__half2*)&g_vh[base + 32] = mkh2(x2a, x2b);
                }
            }
        }
    }
}

// ---------------------------------------------------------------------------
// Flash attention on mma.sync, occ 2.  Softmax scalar-thinned:
//  - exp2-fold: p = exp2f(fma(s, C, -m*C)), C = 0.125*log2(e)  (raw scores)
//  - max-skip: when a row's max doesn't grow, sc == 1 exactly -> skip rescale
//  - single __syncthreads per chunk (wait -> sync -> prefetch -> compute)
// ---------------------------------------------------------------------------
#define FA_BUF  16384u
#define FA_SMEM (32768 + 2*16384)
#define EXPC    0.180336879f   // 0.125 * log2(e)

__device__ __forceinline__ void fa_load_kv(const __half* kh, const __half* vb,
                                           int k0, uint32_t sb, int buf, int tid)
{
    #pragma unroll
    for (int j = 0; j < 2; ++j) {
        int u = tid + j * 256;          // 0..511
        int r = u >> 3, c = u & 7;
        uint32_t so = sb + 32768u + (uint32_t)buf * FA_BUF
                    + (uint32_t)r * 128u + ((uint32_t)(c ^ (r & 7)) << 4);
        cp16(so,         &kh[(size_t)(k0 + r) * 64u + c * 8]);
        cp16(so + 8192u, &vb[(size_t)(k0 + r) * 64u + c * 8]);
    }
    asm volatile("cp.async.commit_group;" ::: "memory");
}

__global__ __launch_bounds__(256, 2) void flash_mma()
{
    extern __shared__ char smem[];
    const uint32_t sb = s2u(smem);
    const int tid  = threadIdx.x;
    const int lane = tid & 31;
    const int wid  = tid >> 5;
    const int q0   = blockIdx.x << 7;
    const int h    = blockIdx.y;
    const int b    = blockIdx.z;
    const int kvh  = h >> 2;

    const __half* qhib = g_qhi + ((size_t)(b*NH_ + h)*S_ + q0)*D_;
    const __half* qlob = g_qlo + ((size_t)(b*NH_ + h)*S_ + q0)*D_;
    const __half* khb  = g_kh  + ((size_t)(b*NKV_ + kvh)*S_)*D_;
    const __half* vbb  = g_vh  + ((size_t)(b*NKV_ + kvh)*S_)*D_;

    #pragma unroll
    for (int j = 0; j < 4; ++j) {
        int u = tid + j * 256;              // 0..1023
        int r = u >> 3, c = u & 7;
        uint32_t so = (uint32_t)r * 128u + ((uint32_t)(c ^ (r & 7)) << 4);
        cp16(sb + so,          &qhib[(size_t)r * 64u + c * 8]);
        cp16(sb + 16384u + so, &qlob[(size_t)r * 64u + c * 8]);
    }
    fa_load_kv(khb, vbb, 0, sb, 0, tid);   // group: [Q + KV0]

    float oacc[8][4];
    #pragma unroll
    for (int dt = 0; dt < 8; ++dt)
        #pragma unroll
        for (int j = 0; j < 4; ++j) oacc[dt][j] = 0.f;
    float m0 = -INFINITY, m1 = -INFINITY, l0 = 0.f, l1 = 0.f;   // m in RAW score units

    const int wrow = wid * 16;
    const uint32_t KH = sb + 32768u;

    for (int c = 0; c < 32; ++c) {
        const int buf = c & 1;
        asm volatile("cp.async.wait_group 0;" ::: "memory");   // chunk c ready
        __syncthreads();                                       // all warps done with c-1
        if (c + 1 < 32)
            fa_load_kv(khb, vbb, (c + 1) * 64, sb, buf ^ 1, tid);

        const uint32_t kh = KH + (uint32_t)buf * FA_BUF;
        const uint32_t vv = kh + 8192u;

        // ---- S = Q K^T (raw scores): hi f32 acc + lo f16 acc ----
        float sacc[8][4];
        uint32_t shl[8][2];
        #pragma unroll
        for (int nt = 0; nt < 8; ++nt) {
            #pragma unroll
            for (int j = 0; j < 4; ++j) sacc[nt][j] = 0.f;
            shl[nt][0] = 0u; shl[nt][1] = 0u;
        }

        #pragma unroll
        for (int ks = 0; ks < 4; ++ks) {
            const int cg = ks * 2 + (lane >> 4);
            int rq = wrow + (lane & 15);
            uint32_t swq = (uint32_t)(cg ^ (rq & 7)) << 4;
            uint32_t aqh[4], aql[4];
            ldsm4(aqh, sb +          (uint32_t)rq * 128u + swq);
            ldsm4(aql, sb + 16384u + (uint32_t)rq * 128u + swq);
            uint32_t bh[8][2];
            #pragma unroll
            for (int kb = 0; kb < 4; ++kb) {
                int rk = kb * 16 + (lane & 15);
                uint32_t swk = (uint32_t)(cg ^ (rk & 7)) << 4;
                uint32_t t[4];
                ldsm4(t, kh + (uint32_t)rk * 128u + swk);
                bh[kb*2  ][0] = t[0]; bh[kb*2  ][1] = t[2];
                bh[kb*2+1][0] = t[1]; bh[kb*2+1][1] = t[3];
            }
            #pragma unroll
            for (int nt = 0; nt < 8; ++nt) mma16816h(sacc[nt], aqh, bh[nt]);
            #pragma unroll
            for (int nt = 0; nt < 8; ++nt) mma16816hacc(shl[nt], aql, bh[nt]);
        }
        #pragma unroll
        for (int nt = 0; nt < 8; ++nt) {
            __half2 p01 = *(__half2*)&shl[nt][0];
            __half2 p23 = *(__half2*)&shl[nt][1];
            sacc[nt][0] += __half2float(p01.x);
            sacc[nt][1] += __half2float(p01.y);
            sacc[nt][2] += __half2float(p23.x);
            sacc[nt][3] += __half2float(p23.y);
        }

        // ---- online softmax on raw scores (exp2-fold + max-skip) ----
        float mx0 = -INFINITY, mx1 = -INFINITY;
        #pragma unroll
        for (int nt = 0; nt < 8; ++nt) {
            mx0 = fmaxf(mx0, fmaxf(sacc[nt][0], sacc[nt][1]));
            mx1 = fmaxf(mx1, fmaxf(sacc[nt][2], sacc[nt][3]));
        }
        #pragma unroll
        for (int off = 1; off < 4; off <<= 1) {
            mx0 = fmaxf(mx0, __shfl_xor_sync(0xffffffffu, mx0, off));
            mx1 = fmaxf(mx1, __shfl_xor_sync(0xffffffffu, mx1, off));
        }
        if (mx0 > m0) {   // new max -> rescale (else sc == 1 exactly, skip)
            float sc0 = exp2f((m0 - mx0) * EXPC);
            m0 = mx0;
            l0 *= sc0;
            #pragma unroll
            for (int dt = 0; dt < 8; ++dt) { oacc[dt][0] *= sc0; oacc[dt][1] *= sc0; }
        }
        if (mx1 > m1) {
            float sc1 = exp2f((m1 - mx1) * EXPC);
            m1 = mx1;
            l1 *= sc1;
            #pragma unroll
            for (int dt = 0; dt < 8; ++dt) { oacc[dt][2] *= sc1; oacc[dt][3] *= sc1; }
        }
        const float nC0 = m0 * EXPC, nC1 = m1 * EXPC;
        float rs0 = 0.f, rs1 = 0.f;
        #pragma unroll
        for (int nt = 0; nt < 8; ++nt) {
            sacc[nt][0] = exp2f(fmaf(sacc[nt][0], EXPC, -nC0));
            sacc[nt][1] = exp2f(fmaf(sacc[nt][1], EXPC, -nC0));
            sacc[nt][2] = exp2f(fmaf(sacc[nt][2], EXPC, -nC1));
            sacc[nt][3] = exp2f(fmaf(sacc[nt][3], EXPC, -nC1));
            rs0 += sacc[nt][0] + sacc[nt][1];
            rs1 += sacc[nt][2] + sacc[nt][3];
        }
        #pragma unroll
        for (int off = 1; off < 4; off <<= 1) {
            rs0 += __shfl_xor_sync(0xffffffffu, rs0, off);
            rs1 += __shfl_xor_sync(0xffffffffu, rs1, off);
        }
        l0 += rs0;
        l1 += rs1;

        // ---- O += P V ----
        #pragma unroll
        for (int ks = 0; ks < 4; ++ks) {
            uint32_t pa[4];
            pa[0] = packf16(sacc[2*ks  ][0], sacc[2*ks  ][1]);
            pa[1] = packf16(sacc[2*ks  ][2], sacc[2*ks  ][3]);
            pa[2] = packf16(sacc[2*ks+1][0], sacc[2*ks+1][1]);
            pa[3] = packf16(sacc[2*ks+1][2], sacc[2*ks+1][3]);
            int rv = ks * 16 + (lane & 7) + ((lane >> 3) & 1) * 8;
            uint32_t rvb = vv + (uint32_t)rv * 128u;
            uint32_t bv[8][2];
            #pragma unroll
            for (int dp = 0; dp < 4; ++dp) {
                int cv = dp * 2 + (lane >> 4);
                uint32_t tv[4];
                ldsm4t(tv, rvb + ((uint32_t)(cv ^ (rv & 7)) << 4));
                bv[dp*2  ][0] = tv[0]; bv[dp*2  ][1] = tv[1];
                bv[dp*2+1][0] = tv[2]; bv[dp*2+1][1] = tv[3];
            }
            #pragma unroll
            for (int dt = 0; dt < 8; ++dt)
                mma16816h(oacc[dt], pa, bv[dt]);
        }
    }

    float inv0 = 1.f / l0, inv1 = 1.f / l1;
    const int r0g = q0 + wrow + (lane >> 2);
    const size_t m0i = ((size_t)(b * S_ + r0g)) * 2048u + h * 64;
    const size_t m1i = m0i + 8u * 2048u;
    #pragma unroll
    for (int dt = 0; dt < 8; ++dt) {
        int d = dt * 8 + (lane & 3) * 2;
        float v0 = oacc[dt][0] * inv0, v1 = oacc[dt][1] * inv0;
        float v2 = oacc[dt][2] * inv1, v3 = oacc[dt][3] * inv1;
        __half2 h01 = mkh2(v0, v1), h23 = mkh2(v2, v3);
        *(__half2*)&g_aohi[m0i + d] = h01;
        *(__half2*)&g_aolo[m0i + d] =
            mkh2(v0 - __half2float(h01.x), v1 - __half2float(h01.y));
        *(__half2*)&g_aohi[m1i + d] = h23;
        *(__half2*)&g_aolo[m1i + d] =
            mkh2(v2 - __half2float(h23.x), v3 - __half2float(h23.y));
    }
}

// ---------------------------------------------------------------------------
extern "C" void kernel_launch(void* const* d_in, const int* in_sizes, int n_in,
                              void* d_out, int out_size)
{
    (void)in_sizes; (void)n_in; (void)out_size;
    const float* hs   = (const float*)d_in[0];
    const float* cosp = (const float*)d_in[1];
    const float* sinp = (const float*)d_in[2];
    const float* Wq = (const float*)d_in[4];
    const float* Wk = (const float*)d_in[5];
    const float* Wv = (const float*)d_in[6];
    const float* Wo = (const float*)d_in[7];
    float* out = (float*)d_out;

    __half *xhi, *xlo, *wh, *woh, *aohi, *aolo;
    cudaGetSymbolAddress((void**)&xhi,  g_xhi);  cudaGetSymbolAddress((void**)&xlo,  g_xlo);
    cudaGetSymbolAddress((void**)&wh,   g_wh);   cudaGetSymbolAddress((void**)&woh,  g_woh);
    cudaGetSymbolAddress((void**)&aohi, g_aohi); cudaGetSymbolAddress((void**)&aolo, g_aolo);

    const int T = 256;
    // 1) all conversions in one launch
    prep_all<<<(PREP_TOT + T-1)/T, T>>>(hs, Wq, Wk, Wv, Wo, xhi, xlo, wh, woh);

    // 2) QKV projection with fused RoPE + fp16 epilogue
    const int gsmem = 2 * 24576;
    cudaFuncSetAttribute(gemm_mma, cudaFuncAttributeMaxDynamicSharedMemorySize, gsmem);
    dim3 g1(3072/128, 4096/128);
    gemm_mma<<<g1, 256, gsmem>>>(xhi, xlo, wh, cosp, sinp, 0, nullptr);

    // 3) Flash attention (occ 2, thinned softmax)
    cudaFuncSetAttribute(flash_mma, cudaFuncAttributeMaxDynamicSharedMemorySize, FA_SMEM);
    dim3 g2(S_/128, NH_, B_);
    flash_mma<<<g2, 256, FA_SMEM>>>();

    // 4) O-projection
    dim3 g3(2048/128, 4096/128);
    gemm_mma<<<g3, 256, gsmem>>>(aohi, aolo, woh, nullptr, nullptr, 1, out);
}

// round 16
// speedup vs baseline: 1.1655x; 1.0149x over previous
#include <cuda_runtime.h>
#include <cuda_bf16.h>
#include <cuda_fp16.h>
#include <math.h>
#include <stdint.h>

#define B_   2
#define S_   2048
#define HID_ 2048
#define NH_  32
#define NKV_ 8
#define D_   64

// ---------------------------------------------------------------------------
// Device scratch (no allocations allowed)
// ---------------------------------------------------------------------------
__device__ __half g_qhi[B_*NH_ *S_*D_], g_qlo[B_*NH_ *S_*D_];  // Q fp16 hi/lo (post-RoPE)
__device__ __half g_kh [B_*NKV_*S_*D_];                        // K fp16 (post-RoPE)
__device__ __half g_vh [B_*NKV_*S_*D_];

__device__ __half g_xhi [4096*2048], g_xlo [4096*2048];   // X hi/lo (fp16)
__device__ __half g_wh  [3072*2048];                      // Wq|Wk|Wv fp16
__device__ __half g_woh [2048*2048];                      // Wo fp16
__device__ __half g_aohi[4096*2048], g_aolo[4096*2048];   // attention out hi/lo

// ---------------------------------------------------------------------------
// Baseline-PTX tensor helpers (NO tcgen05 — harness builds plain compute_103)
// ---------------------------------------------------------------------------
__device__ __forceinline__ uint32_t s2u(const void* p) {
    uint32_t a;
    asm("{ .reg .u64 t; cvta.to.shared.u64 t, %1; cvt.u32.u64 %0, t; }"
        : "=r"(a) : "l"(p));
    return a;
}
__device__ __forceinline__ void ldsm4(uint32_t* r, uint32_t addr) {
    asm volatile("ldmatrix.sync.aligned.m8n8.x4.shared.b16 {%0,%1,%2,%3}, [%4];"
        : "=r"(r[0]), "=r"(r[1]), "=r"(r[2]), "=r"(r[3]) : "r"(addr));
}
__device__ __forceinline__ void ldsm4t(uint32_t* r, uint32_t addr) {
    asm volatile("ldmatrix.sync.aligned.m8n8.x4.trans.shared.b16 {%0,%1,%2,%3}, [%4];"
        : "=r"(r[0]), "=r"(r[1]), "=r"(r[2]), "=r"(r[3]) : "r"(addr));
}
__device__ __forceinline__ void mma16816h(float* c, const uint32_t* a, const uint32_t* b) {
    asm volatile("mma.sync.aligned.m16n8k16.row.col.f32.f16.f16.f32 "
        "{%0,%1,%2,%3}, {%4,%5,%6,%7}, {%8,%9}, {%0,%1,%2,%3};"
        : "+f"(c[0]), "+f"(c[1]), "+f"(c[2]), "+f"(c[3])
        : "r"(a[0]), "r"(a[1]), "r"(a[2]), "r"(a[3]), "r"(b[0]), "r"(b[1]));
}
__device__ __forceinline__ void mma16816hacc(uint32_t* c, const uint32_t* a, const uint32_t* b) {
    asm volatile("mma.sync.aligned.m16n8k16.row.col.f16.f16.f16.f16 "
        "{%0,%1}, {%2,%3,%4,%5}, {%6,%7}, {%0,%1};"
        : "+r"(c[0]), "+r"(c[1])
        : "r"(a[0]), "r"(a[1]), "r"(a[2]), "r"(a[3]), "r"(b[0]), "r"(b[1]));
}
__device__ __forceinline__ void cp16(uint32_t saddr, const void* gaddr) {
    asm volatile("cp.async.cg.shared.global [%0], [%1], 16;"
                 :: "r"(saddr), "l"(gaddr));
}
__device__ __forceinline__ uint32_t packf16(float lo, float hi) {
    uint32_t d;
    asm("cvt.rn.f16x2.f32 %0, %1, %2;" : "=r"(d) : "f"(hi), "f"(lo));
    return d;
}
__device__ __forceinline__ __half2 mkh2(float a, float b) {
    __half2 h; h.x = __float2half(a); h.y = __float2half(b); return h;
}

// ---------------------------------------------------------------------------
// Prep: X -> fp16 hi/lo split AND all weights -> fp16, one kernel.
// ---------------------------------------------------------------------------
#define X_F2  (4096*2048/2)
#define WQ_F2 (2048*2048/2)
#define WK_F2 ( 512*2048/2)
#define PREP_TOT (X_F2 + 2*WQ_F2 + 2*WK_F2)

__global__ void prep_all(const float* __restrict__ hs,
                         const float* __restrict__ Wq, const float* __restrict__ Wk,
                         const float* __restrict__ Wv, const float* __restrict__ Wo,
                         __half* __restrict__ xhi, __half* __restrict__ xlo,
                         __half* __restrict__ wh,  __half* __restrict__ woh)
{
    int i = blockIdx.x * blockDim.x + threadIdx.x;
    if (i < X_F2) {
        float2 v = ((const float2*)hs)[i];
        __half h0 = __float2half(v.x);
        __half h1 = __float2half(v.y);
        __half2 hh; hh.x = h0; hh.y = h1;
        __half2 ll; ll.x = __float2half(v.x - __half2float(h0));
        ll.y = __float2half(v.y - __half2float(h1));
        ((__half2*)xhi)[i] = hh;
        ((__half2*)xlo)[i] = ll;
        return;
    }
    int k = i - X_F2;
    const float2* src; __half* dst; int j;
    if (k < WQ_F2)                  { src = (const float2*)Wq; dst = wh;             j = k; }
    else if (k < WQ_F2 + WK_F2)     { src = (const float2*)Wk; dst = wh + 2048*2048; j = k - WQ_F2; }
    else if (k < WQ_F2 + 2*WK_F2)   { src = (const float2*)Wv; dst = wh + 2560*2048; j = k - WQ_F2 - WK_F2; }
    else if (k < 2*WQ_F2 + 2*WK_F2) { src = (const float2*)Wo; dst = woh;            j = k - WQ_F2 - 2*WK_F2; }
    else return;
    float2 v = src[j];
    __half2 h; h.x = __float2half(v.x); h.y = __float2half(v.y);
    ((__half2*)dst)[j] = h;
}

// ---------------------------------------------------------------------------
// fp32-emulated GEMM on fp16 mma.sync, 2 MMAs/k-step:
//   C = (A_hi + A_lo) * fp16(B)
// 128x128 CTA tile, K-chunk 64 (4 k-steps per barrier), 8 warps (4x2), occ 2.
// SMEM/buffer: Ahi 16K | Alo 16K | B 16K = 48KB, double buffered = 96KB/CTA.
// Swizzle: rows of 128B; 16B group c (0..7) at row r -> c ^ (r & 7).
// mode 0: fused RoPE + fp16 q/k/v epilogue; mode 1: fp32 outp.
// ---------------------------------------------------------------------------
#define NCHUNK 32      // 2048 / 64
#define GBUF   49152u

__device__ __forceinline__ void load_chunk(
    const __half* __restrict__ Ahi, const __half* __restrict__ Alo,
    const __half* __restrict__ Bh,
    int m0, int n0, uint32_t sb, int buf, int chunk, int tid)
{
    const __half* srcs[3] = {Ahi, Alo, Bh};
    const int r0s[3] = {m0, m0, n0};
    #pragma unroll
    for (int op = 0; op < 3; ++op) {
        #pragma unroll
        for (int j = 0; j < 4; ++j) {
            int u = tid + j * 256;           // 0..1023
            int r = u >> 3, c = u & 7;
            const __half* g =
                srcs[op] + (size_t)(r0s[op] + r) * 2048u + chunk * 64 + c * 8;
            uint32_t so = sb + (uint32_t)buf * GBUF + (uint32_t)op * 16384u
                        + (uint32_t)r * 128u
                        + ((uint32_t)(c ^ (r & 7)) << 4);
            cp16(so, g);
        }
    }
    asm volatile("cp.async.commit_group;" ::: "memory");
}

__global__ __launch_bounds__(256, 2) void gemm_mma(
    const __half* __restrict__ Ahi, const __half* __restrict__ Alo,
    const __half* __restrict__ Bh,
    const float* __restrict__ cosp, const float* __restrict__ sinp,
    int mode, float* __restrict__ outp)
{
    extern __shared__ char smem[];
    const uint32_t sb = s2u(smem);
    const int tid  = threadIdx.x;
    const int lane = tid & 31;
    const int wid  = tid >> 5;
    const int wm   = wid & 3;
    const int wn   = wid >> 2;
    const int m0   = blockIdx.y << 7;
    const int n0   = blockIdx.x << 7;

    float acc[2][8][4];
    #pragma unroll
    for (int mt = 0; mt < 2; ++mt)
        #pragma unroll
        for (int nt = 0; nt < 8; ++nt)
            #pragma unroll
            for (int j = 0; j < 4; ++j) acc[mt][nt][j] = 0.f;

    load_chunk(Ahi, Alo, Bh, m0, n0, sb, 0, 0, tid);

    for (int c = 0; c < NCHUNK; ++c) {
        const int buf = c & 1;
        asm volatile("cp.async.wait_group 0;" ::: "memory");   // chunk c complete
        __syncthreads();                                       // all warps done with c-1
        if (c + 1 < NCHUNK)
            load_chunk(Ahi, Alo, Bh, m0, n0, sb, buf ^ 1, c + 1, tid);

        const uint32_t base = sb + (uint32_t)buf * GBUF;
        #pragma unroll
        for (int ks = 0; ks < 4; ++ks) {
            const int cg = ks * 2 + (lane >> 4);
            uint32_t ah[2][4], al[2][4];
            #pragma unroll
            for (int mt = 0; mt < 2; ++mt) {
                int r = wm * 32 + mt * 16 + (lane & 15);
                uint32_t sw = (uint32_t)(cg ^ (r & 7)) << 4;
                ldsm4(ah[mt], base +      0u + (uint32_t)r * 128u + sw);
                ldsm4(al[mt], base + 16384u + (uint32_t)r * 128u + sw);
            }
            uint32_t bh[8][2];
            #pragma unroll
            for (int nt2 = 0; nt2 < 4; ++nt2) {
                int r = wn * 64 + nt2 * 16 + (lane & 15);
                uint32_t sw = (uint32_t)(cg ^ (r & 7)) << 4;
                uint32_t t[4];
                ldsm4(t, base + 32768u + (uint32_t)r * 128u + sw);
                bh[nt2*2  ][0] = t[0]; bh[nt2*2  ][1] = t[2];
                bh[nt2*2+1][0] = t[1]; bh[nt2*2+1][1] = t[3];
            }
            #pragma unroll
            for (int mt = 0; mt < 2; ++mt)
                #pragma unroll
                for (int nt = 0; nt < 8; ++nt) {
                    mma16816h(acc[mt][nt], ah[mt], bh[nt]);
                    mma16816h(acc[mt][nt], al[mt], bh[nt]);
                }
        }
    }

    if (mode == 1) {
        #pragma unroll
        for (int mt = 0; mt < 2; ++mt)
            #pragma unroll
            for (int half = 0; half < 2; ++half) {
                const int m = m0 + wm * 32 + mt * 16 + (lane >> 2) + half * 8;
                #pragma unroll
                for (int nt = 0; nt < 8; ++nt) {
                    const int n = n0 + wn * 64 + nt * 8 + (lane & 3) * 2;
                    *(float2*)&outp[(size_t)m * 2048 + n] =
                        make_float2(acc[mt][nt][half*2], acc[mt][nt][half*2+1]);
                }
            }
        return;
    }

    // mode 0: fused RoPE (Q/K) + fp16 conversion.
    #pragma unroll
    for (int mt = 0; mt < 2; ++mt) {
        #pragma unroll
        for (int half = 0; half < 2; ++half) {
            const int m  = m0 + wm * 32 + mt * 16 + (lane >> 2) + half * 8;
            const int bb = m >> 11;
            const int s  = m & 2047;
            const size_t cb = ((size_t)bb * S_ + s) * D_;
            #pragma unroll
            for (int ntp = 0; ntp < 4; ++ntp) {
                const int n = n0 + wn * 64 + ntp * 8 + (lane & 3) * 2;
                float x1a = acc[mt][ntp  ][half*2], x1b = acc[mt][ntp  ][half*2+1];
                float x2a = acc[mt][ntp+4][half*2], x2b = acc[mt][ntp+4][half*2+1];
                if (n < 2560) {
                    const int nn = (n < 2048) ? n : n - 2048;
                    const int h = nn >> 6, d = nn & 63;
                    float2 c1 = *(const float2*)&cosp[cb + d];
                    float2 c2 = *(const float2*)&cosp[cb + d + 32];
                    float2 s1 = *(const float2*)&sinp[cb + d];
                    float2 s2 = *(const float2*)&sinp[cb + d + 32];
                    float y1a = x1a*c1.x - x2a*s1.x;
                    float y1b = x1b*c1.y - x2b*s1.y;
                    float y2a = x2a*c2.x + x1a*s2.x;
                    float y2b = x2b*c2.y + x1b*s2.y;
                    if (n < 2048) {
                        const size_t base = (((size_t)bb*NH_ + h)*S_ + s)*D_ + d;
                        __half2 h1 = mkh2(y1a, y1b), h2v = mkh2(y2a, y2b);
                        *(__half2*)&g_qhi[base]      = h1;
                        *(__half2*)&g_qhi[base + 32] = h2v;
                        *(__half2*)&g_qlo[base] =
                            mkh2(y1a - __half2float(h1.x),  y1b - __half2float(h1.y));
                        *(__half2*)&g_qlo[base + 32] =
                            mkh2(y2a - __half2float(h2v.x), y2b - __half2float(h2v.y));
                    } else {
                        const size_t base = (((size_t)bb*NKV_ + h)*S_ + s)*D_ + d;
                        *(__half2*)&g_kh[base]      = mkh2(y1a, y1b);
                        *(__half2*)&g_kh[base + 32] = mkh2(y2a, y2b);
                    }
                } else {
                    const int nn = n - 2560;
                    const int h = nn >> 6, d = nn & 63;
                    const size_t base = (((size_t)bb*NKV_ + h)*S_ + s)*D_ + d;
                    *(__half2*)&g_vh[base]      = mkh2(x1a, x1b);
                    *(__half2*)&g_vh[base + 32] = mkh2(x2a, x2b);
                }
            }
        }
    }
}

// ---------------------------------------------------------------------------
// Flash attention on mma.sync, occ 2 (unchanged from passing R15 kernel).
// ---------------------------------------------------------------------------
#define FA_BUF  16384u
#define FA_SMEM (32768 + 2*16384)
#define EXPC    0.180336879f   // 0.125 * log2(e)

__device__ __forceinline__ void fa_load_kv(const __half* kh, const __half* vb,
                                           int k0, uint32_t sb, int buf, int tid)
{
    #pragma unroll
    for (int j = 0; j < 2; ++j) {
        int u = tid + j * 256;          // 0..511
        int r = u >> 3, c = u & 7;
        uint32_t so = sb + 32768u + (uint32_t)buf * FA_BUF
                    + (uint32_t)r * 128u + ((uint32_t)(c ^ (r & 7)) << 4);
        cp16(so,         &kh[(size_t)(k0 + r) * 64u + c * 8]);
        cp16(so + 8192u, &vb[(size_t)(k0 + r) * 64u + c * 8]);
    }
    asm volatile("cp.async.commit_group;" ::: "memory");
}

__global__ __launch_bounds__(256, 2) void flash_mma()
{
    extern __shared__ char smem[];
    const uint32_t sb = s2u(smem);
    const int tid  = threadIdx.x;
    const int lane = tid & 31;
    const int wid  = tid >> 5;
    const int q0   = blockIdx.x << 7;
    const int h    = blockIdx.y;
    const int b    = blockIdx.z;
    const int kvh  = h >> 2;

    const __half* qhib = g_qhi + ((size_t)(b*NH_ + h)*S_ + q0)*D_;
    const __half* qlob = g_qlo + ((size_t)(b*NH_ + h)*S_ + q0)*D_;
    const __half* khb  = g_kh  + ((size_t)(b*NKV_ + kvh)*S_)*D_;
    const __half* vbb  = g_vh  + ((size_t)(b*NKV_ + kvh)*S_)*D_;

    #pragma unroll
    for (int j = 0; j < 4; ++j) {
        int u = tid + j * 256;              // 0..1023
        int r = u >> 3, c = u & 7;
        uint32_t so = (uint32_t)r * 128u + ((uint32_t)(c ^ (r & 7)) << 4);
        cp16(sb + so,          &qhib[(size_t)r * 64u + c * 8]);
        cp16(sb + 16384u + so, &qlob[(size_t)r * 64u + c * 8]);
    }
    fa_load_kv(khb, vbb, 0, sb, 0, tid);   // group: [Q + KV0]

    float oacc[8][4];
    #pragma unroll
    for (int dt = 0; dt < 8; ++dt)
        #pragma unroll
        for (int j = 0; j < 4; ++j) oacc[dt][j] = 0.f;
    float m0 = -INFINITY, m1 = -INFINITY, l0 = 0.f, l1 = 0.f;   // raw-score units

    const int wrow = wid * 16;
    const uint32_t KH = sb + 32768u;

    for (int c = 0; c < 32; ++c) {
        const int buf = c & 1;
        asm volatile("cp.async.wait_group 0;" ::: "memory");
        __syncthreads();
        if (c + 1 < 32)
            fa_load_kv(khb, vbb, (c + 1) * 64, sb, buf ^ 1, tid);

        const uint32_t kh = KH + (uint32_t)buf * FA_BUF;
        const uint32_t vv = kh + 8192u;

        float sacc[8][4];
        uint32_t shl[8][2];
        #pragma unroll
        for (int nt = 0; nt < 8; ++nt) {
            #pragma unroll
            for (int j = 0; j < 4; ++j) sacc[nt][j] = 0.f;
            shl[nt][0] = 0u; shl[nt][1] = 0u;
        }

        #pragma unroll
        for (int ks = 0; ks < 4; ++ks) {
            const int cg = ks * 2 + (lane >> 4);
            int rq = wrow + (lane & 15);
            uint32_t swq = (uint32_t)(cg ^ (rq & 7)) << 4;
            uint32_t aqh[4], aql[4];
            ldsm4(aqh, sb +          (uint32_t)rq * 128u + swq);
            ldsm4(aql, sb + 16384u + (uint32_t)rq * 128u + swq);
            uint32_t bh[8][2];
            #pragma unroll
            for (int kb = 0; kb < 4; ++kb) {
                int rk = kb * 16 + (lane & 15);
                uint32_t swk = (uint32_t)(cg ^ (rk & 7)) << 4;
                uint32_t t[4];
                ldsm4(t, kh + (uint32_t)rk * 128u + swk);
                bh[kb*2  ][0] = t[0]; bh[kb*2  ][1] = t[2];
                bh[kb*2+1][0] = t[1]; bh[kb*2+1][1] = t[3];
            }
            #pragma unroll
            for (int nt = 0; nt < 8; ++nt) mma16816h(sacc[nt], aqh, bh[nt]);
            #pragma unroll
            for (int nt = 0; nt < 8; ++nt) mma16816hacc(shl[nt], aql, bh[nt]);
        }
        #pragma unroll
        for (int nt = 0; nt < 8; ++nt) {
            __half2 p01 = *(__half2*)&shl[nt][0];
            __half2 p23 = *(__half2*)&shl[nt][1];
            sacc[nt][0] += __half2float(p01.x);
            sacc[nt][1] += __half2float(p01.y);
            sacc[nt][2] += __half2float(p23.x);
            sacc[nt][3] += __half2float(p23.y);
        }

        float mx0 = -INFINITY, mx1 = -INFINITY;
        #pragma unroll
        for (int nt = 0; nt < 8; ++nt) {
            mx0 = fmaxf(mx0, fmaxf(sacc[nt][0], sacc[nt][1]));
            mx1 = fmaxf(mx1, fmaxf(sacc[nt][2], sacc[nt][3]));
        }
        #pragma unroll
        for (int off = 1; off < 4; off <<= 1) {
            mx0 = fmaxf(mx0, __shfl_xor_sync(0xffffffffu, mx0, off));
            mx1 = fmaxf(mx1, __shfl_xor_sync(0xffffffffu, mx1, off));
        }
        if (mx0 > m0) {
            float sc0 = exp2f((m0 - mx0) * EXPC);
            m0 = mx0;
            l0 *= sc0;
            #pragma unroll
            for (int dt = 0; dt < 8; ++dt) { oacc[dt][0] *= sc0; oacc[dt][1] *= sc0; }
        }
        if (mx1 > m1) {
            float sc1 = exp2f((m1 - mx1) * EXPC);
            m1 = mx1;
            l1 *= sc1;
            #pragma unroll
            for (int dt = 0; dt < 8; ++dt) { oacc[dt][2] *= sc1; oacc[dt][3] *= sc1; }
        }
        const float nC0 = m0 * EXPC, nC1 = m1 * EXPC;
        float rs0 = 0.f, rs1 = 0.f;
        #pragma unroll
        for (int nt = 0; nt < 8; ++nt) {
            sacc[nt][0] = exp2f(fmaf(sacc[nt][0], EXPC, -nC0));
            sacc[nt][1] = exp2f(fmaf(sacc[nt][1], EXPC, -nC0));
            sacc[nt][2] = exp2f(fmaf(sacc[nt][2], EXPC, -nC1));
            sacc[nt][3] = exp2f(fmaf(sacc[nt][3], EXPC, -nC1));
            rs0 += sacc[nt][0] + sacc[nt][1];
            rs1 += sacc[nt][2] + sacc[nt][3];
        }
        #pragma unroll
        for (int off = 1; off < 4; off <<= 1) {
            rs0 += __shfl_xor_sync(0xffffffffu, rs0, off);
            rs1 += __shfl_xor_sync(0xffffffffu, rs1, off);
        }
        l0 += rs0;
        l1 += rs1;

        #pragma unroll
        for (int ks = 0; ks < 4; ++ks) {
            uint32_t pa[4];
            pa[0] = packf16(sacc[2*ks  ][0], sacc[2*ks  ][1]);
            pa[1] = packf16(sacc[2*ks  ][2], sacc[2*ks  ][3]);
            pa[2] = packf16(sacc[2*ks+1][0], sacc[2*ks+1][1]);
            pa[3] = packf16(sacc[2*ks+1][2], sacc[2*ks+1][3]);
            int rv = ks * 16 + (lane & 7) + ((lane >> 3) & 1) * 8;
            uint32_t rvb = vv + (uint32_t)rv * 128u;
            uint32_t bv[8][2];
            #pragma unroll
            for (int dp = 0; dp < 4; ++dp) {
                int cv = dp * 2 + (lane >> 4);
                uint32_t tv[4];
                ldsm4t(tv, rvb + ((uint32_t)(cv ^ (rv & 7)) << 4));
                bv[dp*2  ][0] = tv[0]; bv[dp*2  ][1] = tv[1];
                bv[dp*2+1][0] = tv[2]; bv[dp*2+1][1] = tv[3];
            }
            #pragma unroll
            for (int dt = 0; dt < 8; ++dt)
                mma16816h(oacc[dt], pa, bv[dt]);
        }
    }

    float inv0 = 1.f / l0, inv1 = 1.f / l1;
    const int r0g = q0 + wrow + (lane >> 2);
    const size_t m0i = ((size_t)(b * S_ + r0g)) * 2048u + h * 64;
    const size_t m1i = m0i + 8u * 2048u;
    #pragma unroll
    for (int dt = 0; dt < 8; ++dt) {
        int d = dt * 8 + (lane & 3) * 2;
        float v0 = oacc[dt][0] * inv0, v1 = oacc[dt][1] * inv0;
        float v2 = oacc[dt][2] * inv1, v3 = oacc[dt][3] * inv1;
        __half2 h01 = mkh2(v0, v1), h23 = mkh2(v2, v3);
        *(__half2*)&g_aohi[m0i + d] = h01;
        *(__half2*)&g_aolo[m0i + d] =
            mkh2(v0 - __half2float(h01.x), v1 - __half2float(h01.y));
        *(__half2*)&g_aohi[m1i + d] = h23;
        *(__half2*)&g_aolo[m1i + d] =
            mkh2(v2 - __half2float(h23.x), v3 - __half2float(h23.y));
    }
}

// ---------------------------------------------------------------------------
extern "C" void kernel_launch(void* const* d_in, const int* in_sizes, int n_in,
                              void* d_out, int out_size)
{
    (void)in_sizes; (void)n_in; (void)out_size;
    const float* hs   = (const float*)d_in[0];
    const float* cosp = (const float*)d_in[1];
    const float* sinp = (const float*)d_in[2];
    const float* Wq = (const float*)d_in[4];
    const float* Wk = (const float*)d_in[5];
    const float* Wv = (const float*)d_in[6];
    const float* Wo = (const float*)d_in[7];
    float* out = (float*)d_out;

    __half *xhi, *xlo, *wh, *woh, *aohi, *aolo;
    cudaGetSymbolAddress((void**)&xhi,  g_xhi);  cudaGetSymbolAddress((void**)&xlo,  g_xlo);
    cudaGetSymbolAddress((void**)&wh,   g_wh);   cudaGetSymbolAddress((void**)&woh,  g_woh);
    cudaGetSymbolAddress((void**)&aohi, g_aohi); cudaGetSymbolAddress((void**)&aolo, g_aolo);

    const int T = 256;
    // 1) all conversions in one launch
    prep_all<<<(PREP_TOT + T-1)/T, T>>>(hs, Wq, Wk, Wv, Wo, xhi, xlo, wh, woh);

    // 2) QKV projection with fused RoPE + fp16 epilogue (K-chunk 64)
    const int gsmem = 2 * (int)GBUF;   // 96KB
    cudaFuncSetAttribute(gemm_mma, cudaFuncAttributeMaxDynamicSharedMemorySize, gsmem);
    dim3 g1(3072/128, 4096/128);
    gemm_mma<<<g1, 256, gsmem>>>(xhi, xlo, wh, cosp, sinp, 0, nullptr);

    // 3) Flash attention (occ 2, thinned softmax)
    cudaFuncSetAttribute(flash_mma, cudaFuncAttributeMaxDynamicSharedMemorySize, FA_SMEM);
    dim3 g2(S_/128, NH_, B_);
    flash_mma<<<g2, 256, FA_SMEM>>>();

    // 4) O-projection (K-chunk 64)
    dim3 g3(2048/128, 4096/128);
    gemm_mma<<<g3, 256, gsmem>>>(aohi, aolo, woh, nullptr, nullptr, 1, out);
}